// round 12
// baseline (speedup 1.0000x reference)
#include <cuda_runtime.h>
#include <cuda_fp16.h>
#include <cstdint>

#define D_MODEL 2048
#define NHEADS  16
#define HD      128
#define BATCH   2
#define TQ      1024
#define XLLEN   1024
#define KVLEN   2048
#define MROWS   (BATCH * TQ)    // 2048

// ---------------- scratch (device globals) ----------------
__device__ __half g_yh [(size_t)MROWS * D_MODEL];
__device__ __half g_qh [(size_t)BATCH * NHEADS * TQ * HD];
__device__ __half g_kh [(size_t)BATCH * NHEADS * KVLEN * HD];
__device__ __half g_vh [(size_t)BATCH * NHEADS * KVLEN * HD];
__device__ __half g_ah [(size_t)MROWS * D_MODEL];
__device__ __half g_bh [(size_t)3 * D_MODEL * D_MODEL];
__device__ __half g_bp [(size_t)D_MODEL * D_MODEL];

// ======================= PTX helpers =======================
__device__ __forceinline__ uint32_t smem_u32(const void* p) {
    uint32_t a;
    asm("{ .reg .u64 t; cvta.to.shared.u64 t, %1; cvt.u32.u64 %0, t; }" : "=r"(a) : "l"(p));
    return a;
}
__device__ __forceinline__ void ldm4(uint32_t* r, uint32_t a) {
    asm volatile("ldmatrix.sync.aligned.m8n8.x4.shared.b16 {%0,%1,%2,%3}, [%4];"
                 : "=r"(r[0]), "=r"(r[1]), "=r"(r[2]), "=r"(r[3]) : "r"(a));
}
__device__ __forceinline__ void ldm4t(uint32_t* r, uint32_t a) {
    asm volatile("ldmatrix.sync.aligned.m8n8.x4.trans.shared.b16 {%0,%1,%2,%3}, [%4];"
                 : "=r"(r[0]), "=r"(r[1]), "=r"(r[2]), "=r"(r[3]) : "r"(a));
}
__device__ __forceinline__ void mma16816(float* d, const uint32_t* a, uint32_t b0, uint32_t b1) {
    asm volatile("mma.sync.aligned.m16n8k16.row.col.f32.f16.f16.f32 "
                 "{%0,%1,%2,%3}, {%4,%5,%6,%7}, {%8,%9}, {%0,%1,%2,%3};"
                 : "+f"(d[0]), "+f"(d[1]), "+f"(d[2]), "+f"(d[3])
                 : "r"(a[0]), "r"(a[1]), "r"(a[2]), "r"(a[3]), "r"(b0), "r"(b1));
}
__device__ __forceinline__ void cpa16(uint32_t dst, const void* src) {
    asm volatile("cp.async.cg.shared.global [%0], [%1], 16;" :: "r"(dst), "l"(src));
}
__device__ __forceinline__ void cpa_commit() { asm volatile("cp.async.commit_group;" ::: "memory"); }
__device__ __forceinline__ void cpa_wait2()  { asm volatile("cp.async.wait_group 2;" ::: "memory"); }
__device__ __forceinline__ void cpa_wait1()  { asm volatile("cp.async.wait_group 1;" ::: "memory"); }
__device__ __forceinline__ void cpa_wait0()  { asm volatile("cp.async.wait_group 0;" ::: "memory"); }
// packed-half exp2: one MUFU op for two values; results are P fragments
__device__ __forceinline__ uint32_t ex2h2(float a, float b) {
    __half2 t = __floats2half2_rn(a, b);
    uint32_t u = *(uint32_t*)&t, r;
    asm("ex2.approx.f16x2 %0, %1;" : "=r"(r) : "r"(u));
    return r;
}
__device__ __forceinline__ uint4 cvt8(float4 a, float4 b) {
    __half h[8] = {__float2half_rn(a.x), __float2half_rn(a.y),
                   __float2half_rn(a.z), __float2half_rn(a.w),
                   __float2half_rn(b.x), __float2half_rn(b.y),
                   __float2half_rn(b.z), __float2half_rn(b.w)};
    return *(uint4*)h;
}

// =====================================================================
// prep1: fp32->fp16 for x + wqkv (the qkv GEMM's inputs)
// =====================================================================
__global__ void prep1_kernel(const float* __restrict__ x, const float* __restrict__ wqkv)
{
    const int blk = blockIdx.x;
    const float* src; __half* dst; int i;
    if (blk < 2048) { src = x;    dst = g_ah; i = blk * 256 + threadIdx.x; }
    else            { src = wqkv; dst = g_bh; i = (blk - 2048) * 256 + threadIdx.x; }
    float4 v0 = ((const float4*)src)[2 * i];
    float4 v1 = ((const float4*)src)[2 * i + 1];
    *(uint4*)(dst + (size_t)i * 8) = cvt8(v0, v1);
}

// =====================================================================
// fp16 mma.sync NT GEMM (R9 mainloop): 128x128 CTA tile, BK=32,
// 8 warps (64x32), 5-stage cp.async ring, prefetch distance 3,
// ONE barrier per K-block.  MODE 0: fp32 C.
// MODE 1: fused RoPE + q/k/v scatter; blockIdx.y==16 CTAs are aux
//         workers (wproj conversion + XL K/V prep).
// =====================================================================
#define GTILE_B  10240            // 128 rows x 80B
#define GSTG_B   (2 * GTILE_B)    // A + B
#define GEMM_SMEM (5 * GSTG_B)    // 102400

#define AUX_NW   (D_MODEL * D_MODEL / 8)               // wproj units
#define AUX_NX   (BATCH * XLLEN * D_MODEL / 8)         // XL units
#define AUX_THREADS (48 * 256)

template<int MODE>
__global__ __launch_bounds__(256, 2) void gemm_mma(
    const __half* __restrict__ A, const __half* __restrict__ B,
    float* __restrict__ C, const float* __restrict__ cosb, const float* __restrict__ sinb,
    const float* __restrict__ wproj, const float* __restrict__ kxl,
    const float* __restrict__ vxl, const float* __restrict__ pos,
    int M, int N, int K)
{
    if (MODE == 1 && blockIdx.y == 16) {
        // ---- aux CTAs: wproj fp32->fp16 + XL K/V prep ----
        int tg = blockIdx.x * 256 + threadIdx.x;
        for (int u = tg; u < AUX_NW + AUX_NX; u += AUX_THREADS) {
            if (u < AUX_NW) {
                float4 v0 = ((const float4*)wproj)[2 * u];
                float4 v1 = ((const float4*)wproj)[2 * u + 1];
                *(uint4*)(g_bp + (size_t)u * 8) = cvt8(v0, v1);
            } else {
                int idx = u - AUX_NW;                // (b, t, h, d8)
                int d8 = idx & 15;
                int h  = (idx >> 4) & 15;
                int t  = (idx >> 8) & 1023;
                int b  = idx >> 18;
                size_t src = ((size_t)(b * XLLEN + t)) * D_MODEL + h * HD + d8 * 8;
                size_t ps  = (size_t)t * D_MODEL + h * HD + d8 * 8;
                float4 k0 = *(const float4*)(kxl + src), k1 = *(const float4*)(kxl + src + 4);
                float4 p0 = *(const float4*)(pos + ps),  p1 = *(const float4*)(pos + ps + 4);
                float4 v0 = *(const float4*)(vxl + src), v1 = *(const float4*)(vxl + src + 4);
                k0.x += p0.x; k0.y += p0.y; k0.z += p0.z; k0.w += p0.w;
                k1.x += p1.x; k1.y += p1.y; k1.z += p1.z; k1.w += p1.w;
                size_t dst = ((size_t)((b * NHEADS + h) * KVLEN + t)) * HD + d8 * 8;
                *(uint4*)&g_kh[dst] = cvt8(k0, k1);
                *(uint4*)&g_vh[dst] = cvt8(v0, v1);
            }
        }
        return;
    }

    extern __shared__ __align__(16) char smraw[];
    const uint32_t sb = smem_u32(smraw);
    const int tid = threadIdx.x, wid = tid >> 5, lane = tid & 31;
    const int wm = wid & 1, wn = wid >> 1;
    const int mb = blockIdx.y * 128, nb = blockIdx.x * 128;

    const __half* Asrc = A + (size_t)mb * K;
    const __half* Bsrc = B + (size_t)nb * K;
    const int NKB = K >> 5;
    const int lrow = tid >> 2, lkc = (tid & 3);

    // prologue: stages 0..2 (prefetch distance 3)
#pragma unroll
    for (int s = 0; s < 3; s++) {
        const uint32_t st = sb + s * GSTG_B;
        const int ko = s * 32;
#pragma unroll
        for (int i = 0; i < 2; i++) {
            int row = lrow + i * 64;
            cpa16(st + row * 80 + lkc * 16, Asrc + (size_t)row * K + ko + lkc * 8);
            cpa16(st + GTILE_B + row * 80 + lkc * 16, Bsrc + (size_t)row * K + ko + lkc * 8);
        }
        cpa_commit();
    }

    float acc[4][4][4];
#pragma unroll
    for (int a = 0; a < 4; a++)
#pragma unroll
        for (int b = 0; b < 4; b++)
#pragma unroll
            for (int e = 0; e < 4; e++) acc[a][b][e] = 0.f;

    const uint32_t arow = (uint32_t)(wm * 64 + (lane & 15)) * 80;
    const uint32_t brow = (uint32_t)(wn * 32 + (lane & 15)) * 80;
    const uint32_t lhalf = (lane >> 4) * 16;

    int sc = 0, pc = 3;                               // stage of kb / kb+3
    for (int kb = 0; kb < NKB; kb++) {
        const int rem = NKB - kb - 1;
        if (rem >= 3) cpa_wait2();
        else if (rem == 2) cpa_wait1();
        else cpa_wait0();
        __syncthreads();                               // single barrier per K-block
        const uint32_t st = sb + sc * GSTG_B;

        // ---- ks0 fragment loads ----
        uint32_t Af[4][4], Bf[2][4];
#pragma unroll
        for (int mt = 0; mt < 4; mt++)
            ldm4(Af[mt], st + arow + mt * 16 * 80 + lhalf);
#pragma unroll
        for (int np = 0; np < 2; np++)
            ldm4(Bf[np], st + GTILE_B + brow + np * 16 * 80 + lhalf);

        // ---- prefetch stage kb+3 (LSU work overlaps LDS latency) ----
        if (kb + 3 < NKB) {
            const uint32_t pst = sb + pc * GSTG_B;
            const int ko = (kb + 3) * 32;
#pragma unroll
            for (int i = 0; i < 2; i++) {
                int row = lrow + i * 64;
                cpa16(pst + row * 80 + lkc * 16, Asrc + (size_t)row * K + ko + lkc * 8);
                cpa16(pst + GTILE_B + row * 80 + lkc * 16, Bsrc + (size_t)row * K + ko + lkc * 8);
            }
            cpa_commit();
        }

        // ---- mma ks0 ----
#pragma unroll
        for (int mt = 0; mt < 4; mt++)
#pragma unroll
            for (int nt = 0; nt < 4; nt++)
                mma16816(acc[mt][nt], Af[mt], Bf[nt >> 1][nt & 1], Bf[nt >> 1][(nt & 1) + 2]);

        // ---- ks1 fragment loads + mma ----
#pragma unroll
        for (int mt = 0; mt < 4; mt++)
            ldm4(Af[mt], st + arow + mt * 16 * 80 + 32 + lhalf);
#pragma unroll
        for (int np = 0; np < 2; np++)
            ldm4(Bf[np], st + GTILE_B + brow + np * 16 * 80 + 32 + lhalf);
#pragma unroll
        for (int mt = 0; mt < 4; mt++)
#pragma unroll
            for (int nt = 0; nt < 4; nt++)
                mma16816(acc[mt][nt], Af[mt], Bf[nt >> 1][nt & 1], Bf[nt >> 1][(nt & 1) + 2]);

        sc = (sc == 4) ? 0 : sc + 1;
        pc = (pc == 4) ? 0 : pc + 1;
    }

    if (MODE == 0) {
#pragma unroll
        for (int mt = 0; mt < 4; mt++) {
            int row0 = mb + wm * 64 + mt * 16 + (lane >> 2);
#pragma unroll
            for (int nt = 0; nt < 4; nt++) {
                int col = nb + wn * 32 + nt * 8 + (lane & 3) * 2;
                *(float2*)&C[(size_t)row0 * N + col]       = make_float2(acc[mt][nt][0], acc[mt][nt][1]);
                *(float2*)&C[(size_t)(row0 + 8) * N + col] = make_float2(acc[mt][nt][2], acc[mt][nt][3]);
            }
        }
    } else {
        // fused RoPE + scatter; region (q/k/v) and head are CTA-uniform.
        const int region = nb >> 11;
        const int hh = (nb & 2047) >> 7;
#pragma unroll
        for (int mt = 0; mt < 4; mt++) {
#pragma unroll
            for (int i = 0; i < 2; i++) {
                int row = mb + wm * 64 + mt * 16 + (lane >> 2) + i * 8;
                int bb = row >> 10, t = row & 1023;
#pragma unroll
                for (int nt = 0; nt < 4; nt++) {
                    int d = wn * 32 + nt * 8 + (lane & 3) * 2;
                    float a0 = acc[mt][nt][2 * i], a1 = acc[mt][nt][2 * i + 1];
                    if (region == 2) {
                        size_t dst = ((size_t)(bb * NHEADS + hh) * KVLEN + XLLEN + t) * HD + d;
                        *(__half2*)&g_vh[dst] = __floats2half2_rn(a0, a1);
                    } else {
                        int dp = d >> 1;
                        float cv = cosb[t * 64 + dp], sv = sinb[t * 64 + dp];
                        float o0 = a0 * cv - a1 * sv;
                        float o1 = a0 * sv + a1 * cv;
                        if (region == 0) {
                            size_t dst = ((size_t)(bb * NHEADS + hh) * TQ + t) * HD + d;
                            *(__half2*)&g_qh[dst] = __floats2half2_rn(o0, o1);
                        } else {
                            size_t dst = ((size_t)(bb * NHEADS + hh) * KVLEN + XLLEN + t) * HD + d;
                            *(__half2*)&g_kh[dst] = __floats2half2_rn(o0, o1);
                        }
                    }
                }
            }
        }
    }
}

// =====================================================================
// Flash attention FA2 (R9): BQ=128, BK=128, D=128, 8 warps, 2-stage KV,
// ONE barrier per tile, ex2.approx.f16x2 softmax, P from S regs.
// =====================================================================
#define AQSZ   34816                      // 128 rows x 272B
#define AKV    AQSZ
#define AKVSTG 69632                      // K(128x272) + V(128x272)
#define AVOF   34816
#define ATTN_SMEM (AQSZ + 2 * AKVSTG)     // 174080

__global__ __launch_bounds__(256) void attn_kernel(const int* __restrict__ flag)
{
    extern __shared__ __align__(16) char smraw[];
    const uint32_t sb = smem_u32(smraw);
    const int tid = threadIdx.x, w = tid >> 5, lane = tid & 31;
    const int qt = blockIdx.x, bh = blockIdx.y;
    const int b = bh >> 4, h = bh & 15;
    const int qbase = qt * 128;
    const int causal = *flag;

    const __half* Qh = g_qh + (size_t)bh * (TQ * HD);
    const __half* Kh = g_kh + (size_t)bh * (KVLEN * HD);
    const __half* Vh = g_vh + (size_t)bh * (KVLEN * HD);

    int ntile = causal ? (qt + 9) : 16;
    if (ntile > 16) ntile = 16;

    // Q tile (group 0)
#pragma unroll
    for (int i = 0; i < 8; i++) {
        int c = tid + i * 256;
        int row = c >> 4, kc = c & 15;
        cpa16(sb + row * 272 + kc * 16, Qh + (size_t)(qbase + row) * HD + kc * 8);
    }
    cpa_commit();
    // KV tile 0 (group 1)
    {
#pragma unroll
        for (int i = 0; i < 8; i++) {
            int c = tid + i * 256;
            int row = c >> 4, kc = c & 15;
            cpa16(sb + AKV + row * 272 + kc * 16, Kh + (size_t)row * HD + kc * 8);
            cpa16(sb + AKV + AVOF + row * 272 + kc * 16, Vh + (size_t)row * HD + kc * 8);
        }
        cpa_commit();
    }
    cpa_wait1();                 // Q arrived
    __syncthreads();

    uint32_t qf[8][4];
    {
        const uint32_t qrow = (uint32_t)(w * 16 + (lane & 15)) * 272;
#pragma unroll
        for (int ks = 0; ks < 8; ks++)
            ldm4(qf[ks], sb + qrow + ks * 32 + (lane >> 4) * 16);
    }

    float oacc[16][4];
#pragma unroll
    for (int nq = 0; nq < 16; nq++)
#pragma unroll
        for (int e = 0; e < 4; e++) oacc[nq][e] = 0.f;
    float mrow[2] = {-1e30f, -1e30f}, lrow[2] = {0.f, 0.f};

    const float scale2 = 0.12751879523525493f;   // log2(e)/sqrt(128)
    const int roff = KVLEN - TQ;

    for (int kt = 0; kt < ntile; kt++) {
        cpa_wait0();                              // tile kt fully arrived
        __syncthreads();                          // + all warps done reading kt-1
        const uint32_t kvst = sb + AKV + (kt & 1) * AKVSTG;

        if (kt + 1 < ntile) {                     // prefetch kt+1 into retired buf
            const uint32_t st = sb + AKV + ((kt + 1) & 1) * AKVSTG;
            const int kb0 = (kt + 1) * 128;
#pragma unroll
            for (int i = 0; i < 8; i++) {
                int c = tid + i * 256;
                int row = c >> 4, kc = c & 15;
                cpa16(st + row * 272 + kc * 16, Kh + (size_t)(kb0 + row) * HD + kc * 8);
                cpa16(st + AVOF + row * 272 + kc * 16, Vh + (size_t)(kb0 + row) * HD + kc * 8);
            }
            cpa_commit();
        }

        // ---- S = Q K^T ----
        float sacc[16][4];
#pragma unroll
        for (int nt = 0; nt < 16; nt++)
#pragma unroll
            for (int e = 0; e < 4; e++) sacc[nt][e] = 0.f;

        const uint32_t krow = (uint32_t)(lane & 15) * 272;
#pragma unroll
        for (int ks = 0; ks < 8; ks++) {
            const uint32_t koff = ks * 32 + (lane >> 4) * 16;
#pragma unroll
            for (int np = 0; np < 8; np++) {
                uint32_t kf[4];
                ldm4(kf, kvst + krow + np * 16 * 272 + koff);
                mma16816(sacc[2 * np],     qf[ks], kf[0], kf[2]);
                mma16816(sacc[2 * np + 1], qf[ks], kf[1], kf[3]);
            }
        }

        // ---- scale (log2 domain); causal mask under uniform branch ----
#pragma unroll
        for (int nt = 0; nt < 16; nt++)
#pragma unroll
            for (int e = 0; e < 4; e++) sacc[nt][e] *= scale2;
        if (causal) {
            const int kbase = kt * 128;
            const int rglo = qbase + w * 16 + (lane >> 2) + roff;
#pragma unroll
            for (int nt = 0; nt < 16; nt++)
#pragma unroll
                for (int e = 0; e < 4; e++) {
                    int cl = kbase + nt * 8 + (lane & 3) * 2 + (e & 1);
                    if (cl > rglo + (e >> 1) * 8) sacc[nt][e] = -1e30f;
                }
        }

        // ---- register softmax (quad shfl) ----
        float ml[2] = {-1e30f, -1e30f};
#pragma unroll
        for (int nt = 0; nt < 16; nt++) {
            ml[0] = fmaxf(ml[0], fmaxf(sacc[nt][0], sacc[nt][1]));
            ml[1] = fmaxf(ml[1], fmaxf(sacc[nt][2], sacc[nt][3]));
        }
#pragma unroll
        for (int i = 0; i < 2; i++) {
            ml[i] = fmaxf(ml[i], __shfl_xor_sync(0xffffffffu, ml[i], 1));
            ml[i] = fmaxf(ml[i], __shfl_xor_sync(0xffffffffu, ml[i], 2));
        }
        float mn[2], al[2];
#pragma unroll
        for (int i = 0; i < 2; i++) {
            mn[i] = fmaxf(mrow[i], ml[i]);
            al[i] = exp2f(mrow[i] - mn[i]);
            mrow[i] = mn[i];
        }

        // ---- P = exp2(S - m) packed fp16; directly PV A-fragments ----
        float ls[2] = {0.f, 0.f};
        uint32_t pf[8][4];
#pragma unroll
        for (int nt = 0; nt < 16; nt++) {
            uint32_t p01 = ex2h2(sacc[nt][0] - mn[0], sacc[nt][1] - mn[0]);
            uint32_t p23 = ex2h2(sacc[nt][2] - mn[1], sacc[nt][3] - mn[1]);
            pf[nt >> 1][(nt & 1) * 2 + 0] = p01;
            pf[nt >> 1][(nt & 1) * 2 + 1] = p23;
            float2 f0 = __half22float2(*(__half2*)&p01);
            float2 f1 = __half22float2(*(__half2*)&p23);
            ls[0] += f0.x + f0.y;
            ls[1] += f1.x + f1.y;
        }
#pragma unroll
        for (int i = 0; i < 2; i++) {
            ls[i] += __shfl_xor_sync(0xffffffffu, ls[i], 1);
            ls[i] += __shfl_xor_sync(0xffffffffu, ls[i], 2);
            lrow[i] = lrow[i] * al[i] + ls[i];
        }
#pragma unroll
        for (int nq = 0; nq < 16; nq++) {
            oacc[nq][0] *= al[0]; oacc[nq][1] *= al[0];
            oacc[nq][2] *= al[1]; oacc[nq][3] *= al[1];
        }

        // ---- O += P V ----
#pragma unroll
        for (int kp = 0; kp < 8; kp++) {
            const uint32_t vrow = (uint32_t)(kp * 16 + (lane & 15)) * 272 + (lane >> 4) * 16;
#pragma unroll
            for (int np = 0; np < 8; np++) {
                uint32_t vb[4];
                ldm4t(vb, kvst + AVOF + vrow + np * 32);
                mma16816(oacc[2 * np],     pf[kp], vb[0], vb[1]);
                mma16816(oacc[2 * np + 1], pf[kp], vb[2], vb[3]);
            }
        }
    }

    // ---- epilogue: O / l -> fp16 y ----
#pragma unroll
    for (int i = 0; i < 2; i++) {
        float inv = 1.0f / lrow[i];
        int rl = w * 16 + (lane >> 2) + i * 8;
        __half* Yp = g_yh + (size_t)(b * TQ + qbase + rl) * D_MODEL + h * HD;
#pragma unroll
        for (int nq = 0; nq < 16; nq++) {
            int col = nq * 8 + (lane & 3) * 2;
            *(__half2*)(Yp + col) =
                __floats2half2_rn(oacc[nq][2 * i] * inv, oacc[nq][2 * i + 1] * inv);
        }
    }
}

// =====================================================================
// launch
// =====================================================================
extern "C" void kernel_launch(void* const* d_in, const int* in_sizes, int n_in,
                              void* d_out, int out_size)
{
    const float* x     = (const float*)d_in[0];
    const float* cosb  = (const float*)d_in[1];
    const float* sinb  = (const float*)d_in[2];
    const float* kxl   = (const float*)d_in[3];
    const float* vxl   = (const float*)d_in[4];
    const float* pos   = (const float*)d_in[5];
    const float* wqkv  = (const float*)d_in[6];
    const float* wproj = (const float*)d_in[7];
    const int*   flag  = (const int*)d_in[8];
    float*       out   = (float*)d_out;

    __half *ah, *bh, *bp, *yh;
    cudaGetSymbolAddress((void**)&ah, g_ah);
    cudaGetSymbolAddress((void**)&bh, g_bh);
    cudaGetSymbolAddress((void**)&bp, g_bp);
    cudaGetSymbolAddress((void**)&yh, g_yh);

    cudaFuncSetAttribute(attn_kernel, cudaFuncAttributeMaxDynamicSharedMemorySize, ATTN_SMEM);
    cudaFuncSetAttribute(gemm_mma<0>, cudaFuncAttributeMaxDynamicSharedMemorySize, GEMM_SMEM);
    cudaFuncSetAttribute(gemm_mma<1>, cudaFuncAttributeMaxDynamicSharedMemorySize, GEMM_SMEM);

    // 1) convert x + wqkv (qkv GEMM inputs)
    prep1_kernel<<<8192, 256>>>(x, wqkv);

    // 2) qkv GEMM (fused RoPE + scatter) + overlapped aux CTAs
    gemm_mma<1><<<dim3(3 * D_MODEL / 128, MROWS / 128 + 1), 256, GEMM_SMEM>>>(
        ah, bh, nullptr, cosb, sinb, wproj, kxl, vxl, pos,
        MROWS, 3 * D_MODEL, D_MODEL);

    // 3) flash attention -> fp16 y
    attn_kernel<<<dim3(TQ / 128, BATCH * NHEADS), 256, ATTN_SMEM>>>(flag);

    // 4) out = y @ w_proj^T
    gemm_mma<0><<<dim3(D_MODEL / 128, MROWS / 128), 256, GEMM_SMEM>>>(
        yh, bp, out, nullptr, nullptr, nullptr, nullptr, nullptr, nullptr,
        MROWS, D_MODEL, D_MODEL);
}

// round 13
// speedup vs baseline: 1.5285x; 1.5285x over previous
#include <cuda_runtime.h>
#include <cuda_fp16.h>
#include <cstdint>

#define D_MODEL 2048
#define NHEADS  16
#define HD      128
#define BATCH   2
#define TQ      1024
#define XLLEN   1024
#define KVLEN   2048
#define MROWS   (BATCH * TQ)    // 2048

// ---------------- scratch (device globals) ----------------
__device__ __half g_yh [(size_t)MROWS * D_MODEL];
__device__ __half g_qh [(size_t)BATCH * NHEADS * TQ * HD];
__device__ __half g_kh [(size_t)BATCH * NHEADS * KVLEN * HD];
__device__ __half g_vh [(size_t)BATCH * NHEADS * KVLEN * HD];
__device__ __half g_ah [(size_t)MROWS * D_MODEL];
__device__ __half g_bh [(size_t)3 * D_MODEL * D_MODEL];
__device__ __half g_bp [(size_t)D_MODEL * D_MODEL];

// ======================= PTX helpers =======================
__device__ __forceinline__ uint32_t smem_u32(const void* p) {
    uint32_t a;
    asm("{ .reg .u64 t; cvta.to.shared.u64 t, %1; cvt.u32.u64 %0, t; }" : "=r"(a) : "l"(p));
    return a;
}
__device__ __forceinline__ void ldm4(uint32_t* r, uint32_t a) {
    asm volatile("ldmatrix.sync.aligned.m8n8.x4.shared.b16 {%0,%1,%2,%3}, [%4];"
                 : "=r"(r[0]), "=r"(r[1]), "=r"(r[2]), "=r"(r[3]) : "r"(a));
}
__device__ __forceinline__ void ldm4t(uint32_t* r, uint32_t a) {
    asm volatile("ldmatrix.sync.aligned.m8n8.x4.trans.shared.b16 {%0,%1,%2,%3}, [%4];"
                 : "=r"(r[0]), "=r"(r[1]), "=r"(r[2]), "=r"(r[3]) : "r"(a));
}
__device__ __forceinline__ void mma16816(float* d, const uint32_t* a, uint32_t b0, uint32_t b1) {
    asm volatile("mma.sync.aligned.m16n8k16.row.col.f32.f16.f16.f32 "
                 "{%0,%1,%2,%3}, {%4,%5,%6,%7}, {%8,%9}, {%0,%1,%2,%3};"
                 : "+f"(d[0]), "+f"(d[1]), "+f"(d[2]), "+f"(d[3])
                 : "r"(a[0]), "r"(a[1]), "r"(a[2]), "r"(a[3]), "r"(b0), "r"(b1));
}
__device__ __forceinline__ void cpa16(uint32_t dst, const void* src) {
    asm volatile("cp.async.cg.shared.global [%0], [%1], 16;" :: "r"(dst), "l"(src));
}
__device__ __forceinline__ void cpa_commit() { asm volatile("cp.async.commit_group;" ::: "memory"); }
__device__ __forceinline__ void cpa_wait1()  { asm volatile("cp.async.wait_group 1;" ::: "memory"); }
__device__ __forceinline__ void cpa_wait0()  { asm volatile("cp.async.wait_group 0;" ::: "memory"); }
// packed-half exp2: one MUFU op for two values; results are P fragments
__device__ __forceinline__ uint32_t ex2h2(float a, float b) {
    __half2 t = __floats2half2_rn(a, b);
    uint32_t u = *(uint32_t*)&t, r;
    asm("ex2.approx.f16x2 %0, %1;" : "=r"(r) : "r"(u));
    return r;
}
__device__ __forceinline__ uint4 cvt8(float4 a, float4 b) {
    __half h[8] = {__float2half_rn(a.x), __float2half_rn(a.y),
                   __float2half_rn(a.z), __float2half_rn(a.w),
                   __float2half_rn(b.x), __float2half_rn(b.y),
                   __float2half_rn(b.z), __float2half_rn(b.w)};
    return *(uint4*)h;
}

// =====================================================================
// prep1: fp32->fp16 for x + wqkv (the qkv GEMM's inputs)
// =====================================================================
__global__ void prep1_kernel(const float* __restrict__ x, const float* __restrict__ wqkv)
{
    const int blk = blockIdx.x;
    const float* src; __half* dst; int i;
    if (blk < 2048) { src = x;    dst = g_ah; i = blk * 256 + threadIdx.x; }
    else            { src = wqkv; dst = g_bh; i = (blk - 2048) * 256 + threadIdx.x; }
    float4 v0 = ((const float4*)src)[2 * i];
    float4 v1 = ((const float4*)src)[2 * i + 1];
    *(uint4*)(dst + (size_t)i * 8) = cvt8(v0, v1);
}

// =====================================================================
// fp16 mma.sync NT GEMM (R9 mainloop, verbatim): 128x128 CTA tile,
// BK=32, 8 warps (64x32), 4-stage cp.async ring (kb&3 static index),
// prefetch distance 2, ONE barrier per K-block.
// MODE 0: fp32 C.
// MODE 1: fused RoPE + q/k/v scatter; blockIdx.y==0 CTAs are aux
//         workers (wproj conversion + XL K/V prep) — dispatched FIRST
//         so their output (needed by attention) is hidden under the
//         tensor-bound GEMM waves.  GEMM rows use blockIdx.y-1.
// =====================================================================
#define GTILE_B  10240            // 128 rows x 80B
#define GSTG_B   (2 * GTILE_B)    // A + B
#define GEMM_SMEM (4 * GSTG_B)    // 81920

#define AUX_NW   (D_MODEL * D_MODEL / 8)               // wproj units
#define AUX_NX   (BATCH * XLLEN * D_MODEL / 8)         // XL units
#define AUX_THREADS (48 * 256)

template<int MODE>
__global__ __launch_bounds__(256, 2) void gemm_mma(
    const __half* __restrict__ A, const __half* __restrict__ B,
    float* __restrict__ C, const float* __restrict__ cosb, const float* __restrict__ sinb,
    const float* __restrict__ wproj, const float* __restrict__ kxl,
    const float* __restrict__ vxl, const float* __restrict__ pos,
    int M, int N, int K)
{
    if (MODE == 1 && blockIdx.y == 0) {
        // ---- aux CTAs (first-dispatched): wproj fp32->fp16 + XL K/V prep ----
        int tg = blockIdx.x * 256 + threadIdx.x;
        for (int u = tg; u < AUX_NW + AUX_NX; u += AUX_THREADS) {
            if (u < AUX_NW) {
                float4 v0 = ((const float4*)wproj)[2 * u];
                float4 v1 = ((const float4*)wproj)[2 * u + 1];
                *(uint4*)(g_bp + (size_t)u * 8) = cvt8(v0, v1);
            } else {
                int idx = u - AUX_NW;                // (b, t, h, d8)
                int d8 = idx & 15;
                int h  = (idx >> 4) & 15;
                int t  = (idx >> 8) & 1023;
                int b  = idx >> 18;
                size_t src = ((size_t)(b * XLLEN + t)) * D_MODEL + h * HD + d8 * 8;
                size_t ps  = (size_t)t * D_MODEL + h * HD + d8 * 8;
                float4 k0 = *(const float4*)(kxl + src), k1 = *(const float4*)(kxl + src + 4);
                float4 p0 = *(const float4*)(pos + ps),  p1 = *(const float4*)(pos + ps + 4);
                float4 v0 = *(const float4*)(vxl + src), v1 = *(const float4*)(vxl + src + 4);
                k0.x += p0.x; k0.y += p0.y; k0.z += p0.z; k0.w += p0.w;
                k1.x += p1.x; k1.y += p1.y; k1.z += p1.z; k1.w += p1.w;
                size_t dst = ((size_t)((b * NHEADS + h) * KVLEN + t)) * HD + d8 * 8;
                *(uint4*)&g_kh[dst] = cvt8(k0, k1);
                *(uint4*)&g_vh[dst] = cvt8(v0, v1);
            }
        }
        return;
    }

    extern __shared__ __align__(16) char smraw[];
    const uint32_t sb = smem_u32(smraw);
    const int tid = threadIdx.x, wid = tid >> 5, lane = tid & 31;
    const int wm = wid & 1, wn = wid >> 1;
    const int myrow = (MODE == 1) ? ((int)blockIdx.y - 1) : (int)blockIdx.y;
    const int mb = myrow * 128, nb = blockIdx.x * 128;

    const __half* Asrc = A + (size_t)mb * K;
    const __half* Bsrc = B + (size_t)nb * K;
    const int NKB = K >> 5;
    const int lrow = tid >> 2, lkc = (tid & 3);

    // prologue: stages 0, 1 (prefetch distance 2)
#pragma unroll
    for (int s = 0; s < 2; s++) {
        const uint32_t st = sb + s * GSTG_B;
        const int ko = s * 32;
#pragma unroll
        for (int i = 0; i < 2; i++) {
            int row = lrow + i * 64;
            cpa16(st + row * 80 + lkc * 16, Asrc + (size_t)row * K + ko + lkc * 8);
            cpa16(st + GTILE_B + row * 80 + lkc * 16, Bsrc + (size_t)row * K + ko + lkc * 8);
        }
        cpa_commit();
    }

    float acc[4][4][4];
#pragma unroll
    for (int a = 0; a < 4; a++)
#pragma unroll
        for (int b = 0; b < 4; b++)
#pragma unroll
            for (int e = 0; e < 4; e++) acc[a][b][e] = 0.f;

    const uint32_t arow = (uint32_t)(wm * 64 + (lane & 15)) * 80;
    const uint32_t brow = (uint32_t)(wn * 32 + (lane & 15)) * 80;
    const uint32_t lhalf = (lane >> 4) * 16;

    for (int kb = 0; kb < NKB; kb++) {
        if (kb + 2 < NKB) cpa_wait1(); else cpa_wait0();
        __syncthreads();                               // single barrier per K-block
        const uint32_t st = sb + (kb & 3) * GSTG_B;

        // ---- ks0 fragment loads ----
        uint32_t Af[4][4], Bf[2][4];
#pragma unroll
        for (int mt = 0; mt < 4; mt++)
            ldm4(Af[mt], st + arow + mt * 16 * 80 + lhalf);
#pragma unroll
        for (int np = 0; np < 2; np++)
            ldm4(Bf[np], st + GTILE_B + brow + np * 16 * 80 + lhalf);

        // ---- prefetch stage kb+2 (LSU work overlaps LDS latency) ----
        if (kb + 2 < NKB) {
            const uint32_t pst = sb + ((kb + 2) & 3) * GSTG_B;
            const int ko = (kb + 2) * 32;
#pragma unroll
            for (int i = 0; i < 2; i++) {
                int row = lrow + i * 64;
                cpa16(pst + row * 80 + lkc * 16, Asrc + (size_t)row * K + ko + lkc * 8);
                cpa16(pst + GTILE_B + row * 80 + lkc * 16, Bsrc + (size_t)row * K + ko + lkc * 8);
            }
            cpa_commit();
        }

        // ---- mma ks0 ----
#pragma unroll
        for (int mt = 0; mt < 4; mt++)
#pragma unroll
            for (int nt = 0; nt < 4; nt++)
                mma16816(acc[mt][nt], Af[mt], Bf[nt >> 1][nt & 1], Bf[nt >> 1][(nt & 1) + 2]);

        // ---- ks1 fragment loads + mma ----
#pragma unroll
        for (int mt = 0; mt < 4; mt++)
            ldm4(Af[mt], st + arow + mt * 16 * 80 + 32 + lhalf);
#pragma unroll
        for (int np = 0; np < 2; np++)
            ldm4(Bf[np], st + GTILE_B + brow + np * 16 * 80 + 32 + lhalf);
#pragma unroll
        for (int mt = 0; mt < 4; mt++)
#pragma unroll
            for (int nt = 0; nt < 4; nt++)
                mma16816(acc[mt][nt], Af[mt], Bf[nt >> 1][nt & 1], Bf[nt >> 1][(nt & 1) + 2]);
    }

    if (MODE == 0) {
#pragma unroll
        for (int mt = 0; mt < 4; mt++) {
            int row0 = mb + wm * 64 + mt * 16 + (lane >> 2);
#pragma unroll
            for (int nt = 0; nt < 4; nt++) {
                int col = nb + wn * 32 + nt * 8 + (lane & 3) * 2;
                *(float2*)&C[(size_t)row0 * N + col]       = make_float2(acc[mt][nt][0], acc[mt][nt][1]);
                *(float2*)&C[(size_t)(row0 + 8) * N + col] = make_float2(acc[mt][nt][2], acc[mt][nt][3]);
            }
        }
    } else {
        // fused RoPE + scatter; region (q/k/v) and head are CTA-uniform.
        const int region = nb >> 11;
        const int hh = (nb & 2047) >> 7;
#pragma unroll
        for (int mt = 0; mt < 4; mt++) {
#pragma unroll
            for (int i = 0; i < 2; i++) {
                int row = mb + wm * 64 + mt * 16 + (lane >> 2) + i * 8;
                int bb = row >> 10, t = row & 1023;
#pragma unroll
                for (int nt = 0; nt < 4; nt++) {
                    int d = wn * 32 + nt * 8 + (lane & 3) * 2;
                    float a0 = acc[mt][nt][2 * i], a1 = acc[mt][nt][2 * i + 1];
                    if (region == 2) {
                        size_t dst = ((size_t)(bb * NHEADS + hh) * KVLEN + XLLEN + t) * HD + d;
                        *(__half2*)&g_vh[dst] = __floats2half2_rn(a0, a1);
                    } else {
                        int dp = d >> 1;
                        float cv = cosb[t * 64 + dp], sv = sinb[t * 64 + dp];
                        float o0 = a0 * cv - a1 * sv;
                        float o1 = a0 * sv + a1 * cv;
                        if (region == 0) {
                            size_t dst = ((size_t)(bb * NHEADS + hh) * TQ + t) * HD + d;
                            *(__half2*)&g_qh[dst] = __floats2half2_rn(o0, o1);
                        } else {
                            size_t dst = ((size_t)(bb * NHEADS + hh) * KVLEN + XLLEN + t) * HD + d;
                            *(__half2*)&g_kh[dst] = __floats2half2_rn(o0, o1);
                        }
                    }
                }
            }
        }
    }
}

// =====================================================================
// Flash attention FA2 (R9 verbatim): BQ=128, BK=128, D=128, 8 warps,
// 2-stage KV, ONE barrier per tile, ex2.approx.f16x2 softmax.
// =====================================================================
#define AQSZ   34816                      // 128 rows x 272B
#define AKV    AQSZ
#define AKVSTG 69632                      // K(128x272) + V(128x272)
#define AVOF   34816
#define ATTN_SMEM (AQSZ + 2 * AKVSTG)     // 174080

__global__ __launch_bounds__(256) void attn_kernel(const int* __restrict__ flag)
{
    extern __shared__ __align__(16) char smraw[];
    const uint32_t sb = smem_u32(smraw);
    const int tid = threadIdx.x, w = tid >> 5, lane = tid & 31;
    const int qt = blockIdx.x, bh = blockIdx.y;
    const int b = bh >> 4, h = bh & 15;
    const int qbase = qt * 128;
    const int causal = *flag;

    const __half* Qh = g_qh + (size_t)bh * (TQ * HD);
    const __half* Kh = g_kh + (size_t)bh * (KVLEN * HD);
    const __half* Vh = g_vh + (size_t)bh * (KVLEN * HD);

    int ntile = causal ? (qt + 9) : 16;
    if (ntile > 16) ntile = 16;

    // Q tile (group 0)
#pragma unroll
    for (int i = 0; i < 8; i++) {
        int c = tid + i * 256;
        int row = c >> 4, kc = c & 15;
        cpa16(sb + row * 272 + kc * 16, Qh + (size_t)(qbase + row) * HD + kc * 8);
    }
    cpa_commit();
    // KV tile 0 (group 1)
    {
#pragma unroll
        for (int i = 0; i < 8; i++) {
            int c = tid + i * 256;
            int row = c >> 4, kc = c & 15;
            cpa16(sb + AKV + row * 272 + kc * 16, Kh + (size_t)row * HD + kc * 8);
            cpa16(sb + AKV + AVOF + row * 272 + kc * 16, Vh + (size_t)row * HD + kc * 8);
        }
        cpa_commit();
    }
    cpa_wait1();                 // Q arrived
    __syncthreads();

    uint32_t qf[8][4];
    {
        const uint32_t qrow = (uint32_t)(w * 16 + (lane & 15)) * 272;
#pragma unroll
        for (int ks = 0; ks < 8; ks++)
            ldm4(qf[ks], sb + qrow + ks * 32 + (lane >> 4) * 16);
    }

    float oacc[16][4];
#pragma unroll
    for (int nq = 0; nq < 16; nq++)
#pragma unroll
        for (int e = 0; e < 4; e++) oacc[nq][e] = 0.f;
    float mrow[2] = {-1e30f, -1e30f}, lrow[2] = {0.f, 0.f};

    const float scale2 = 0.12751879523525493f;   // log2(e)/sqrt(128)
    const int roff = KVLEN - TQ;

    for (int kt = 0; kt < ntile; kt++) {
        cpa_wait0();                              // tile kt fully arrived
        __syncthreads();                          // + all warps done reading kt-1
        const uint32_t kvst = sb + AKV + (kt & 1) * AKVSTG;

        if (kt + 1 < ntile) {                     // prefetch kt+1 into retired buf
            const uint32_t st = sb + AKV + ((kt + 1) & 1) * AKVSTG;
            const int kb0 = (kt + 1) * 128;
#pragma unroll
            for (int i = 0; i < 8; i++) {
                int c = tid + i * 256;
                int row = c >> 4, kc = c & 15;
                cpa16(st + row * 272 + kc * 16, Kh + (size_t)(kb0 + row) * HD + kc * 8);
                cpa16(st + AVOF + row * 272 + kc * 16, Vh + (size_t)(kb0 + row) * HD + kc * 8);
            }
            cpa_commit();
        }

        // ---- S = Q K^T ----
        float sacc[16][4];
#pragma unroll
        for (int nt = 0; nt < 16; nt++)
#pragma unroll
            for (int e = 0; e < 4; e++) sacc[nt][e] = 0.f;

        const uint32_t krow = (uint32_t)(lane & 15) * 272;
#pragma unroll
        for (int ks = 0; ks < 8; ks++) {
            const uint32_t koff = ks * 32 + (lane >> 4) * 16;
#pragma unroll
            for (int np = 0; np < 8; np++) {
                uint32_t kf[4];
                ldm4(kf, kvst + krow + np * 16 * 272 + koff);
                mma16816(sacc[2 * np],     qf[ks], kf[0], kf[2]);
                mma16816(sacc[2 * np + 1], qf[ks], kf[1], kf[3]);
            }
        }

        // ---- scale (log2 domain); causal mask under uniform branch ----
#pragma unroll
        for (int nt = 0; nt < 16; nt++)
#pragma unroll
            for (int e = 0; e < 4; e++) sacc[nt][e] *= scale2;
        if (causal) {
            const int kbase = kt * 128;
            const int rglo = qbase + w * 16 + (lane >> 2) + roff;
#pragma unroll
            for (int nt = 0; nt < 16; nt++)
#pragma unroll
                for (int e = 0; e < 4; e++) {
                    int cl = kbase + nt * 8 + (lane & 3) * 2 + (e & 1);
                    if (cl > rglo + (e >> 1) * 8) sacc[nt][e] = -1e30f;
                }
        }

        // ---- register softmax (quad shfl) ----
        float ml[2] = {-1e30f, -1e30f};
#pragma unroll
        for (int nt = 0; nt < 16; nt++) {
            ml[0] = fmaxf(ml[0], fmaxf(sacc[nt][0], sacc[nt][1]));
            ml[1] = fmaxf(ml[1], fmaxf(sacc[nt][2], sacc[nt][3]));
        }
#pragma unroll
        for (int i = 0; i < 2; i++) {
            ml[i] = fmaxf(ml[i], __shfl_xor_sync(0xffffffffu, ml[i], 1));
            ml[i] = fmaxf(ml[i], __shfl_xor_sync(0xffffffffu, ml[i], 2));
        }
        float mn[2], al[2];
#pragma unroll
        for (int i = 0; i < 2; i++) {
            mn[i] = fmaxf(mrow[i], ml[i]);
            al[i] = exp2f(mrow[i] - mn[i]);
            mrow[i] = mn[i];
        }

        // ---- P = exp2(S - m) packed fp16; directly PV A-fragments ----
        float ls[2] = {0.f, 0.f};
        uint32_t pf[8][4];
#pragma unroll
        for (int nt = 0; nt < 16; nt++) {
            uint32_t p01 = ex2h2(sacc[nt][0] - mn[0], sacc[nt][1] - mn[0]);
            uint32_t p23 = ex2h2(sacc[nt][2] - mn[1], sacc[nt][3] - mn[1]);
            pf[nt >> 1][(nt & 1) * 2 + 0] = p01;
            pf[nt >> 1][(nt & 1) * 2 + 1] = p23;
            float2 f0 = __half22float2(*(__half2*)&p01);
            float2 f1 = __half22float2(*(__half2*)&p23);
            ls[0] += f0.x + f0.y;
            ls[1] += f1.x + f1.y;
        }
#pragma unroll
        for (int i = 0; i < 2; i++) {
            ls[i] += __shfl_xor_sync(0xffffffffu, ls[i], 1);
            ls[i] += __shfl_xor_sync(0xffffffffu, ls[i], 2);
            lrow[i] = lrow[i] * al[i] + ls[i];
        }
#pragma unroll
        for (int nq = 0; nq < 16; nq++) {
            oacc[nq][0] *= al[0]; oacc[nq][1] *= al[0];
            oacc[nq][2] *= al[1]; oacc[nq][3] *= al[1];
        }

        // ---- O += P V ----
#pragma unroll
        for (int kp = 0; kp < 8; kp++) {
            const uint32_t vrow = (uint32_t)(kp * 16 + (lane & 15)) * 272 + (lane >> 4) * 16;
#pragma unroll
            for (int np = 0; np < 8; np++) {
                uint32_t vb[4];
                ldm4t(vb, kvst + AVOF + vrow + np * 32);
                mma16816(oacc[2 * np],     pf[kp], vb[0], vb[1]);
                mma16816(oacc[2 * np + 1], pf[kp], vb[2], vb[3]);
            }
        }
    }

    // ---- epilogue: O / l -> fp16 y ----
#pragma unroll
    for (int i = 0; i < 2; i++) {
        float inv = 1.0f / lrow[i];
        int rl = w * 16 + (lane >> 2) + i * 8;
        __half* Yp = g_yh + (size_t)(b * TQ + qbase + rl) * D_MODEL + h * HD;
#pragma unroll
        for (int nq = 0; nq < 16; nq++) {
            int col = nq * 8 + (lane & 3) * 2;
            *(__half2*)(Yp + col) =
                __floats2half2_rn(oacc[nq][2 * i] * inv, oacc[nq][2 * i + 1] * inv);
        }
    }
}

// =====================================================================
// launch
// =====================================================================
extern "C" void kernel_launch(void* const* d_in, const int* in_sizes, int n_in,
                              void* d_out, int out_size)
{
    const float* x     = (const float*)d_in[0];
    const float* cosb  = (const float*)d_in[1];
    const float* sinb  = (const float*)d_in[2];
    const float* kxl   = (const float*)d_in[3];
    const float* vxl   = (const float*)d_in[4];
    const float* pos   = (const float*)d_in[5];
    const float* wqkv  = (const float*)d_in[6];
    const float* wproj = (const float*)d_in[7];
    const int*   flag  = (const int*)d_in[8];
    float*       out   = (float*)d_out;

    __half *ah, *bh, *bp, *yh;
    cudaGetSymbolAddress((void**)&ah, g_ah);
    cudaGetSymbolAddress((void**)&bh, g_bh);
    cudaGetSymbolAddress((void**)&bp, g_bp);
    cudaGetSymbolAddress((void**)&yh, g_yh);

    cudaFuncSetAttribute(attn_kernel, cudaFuncAttributeMaxDynamicSharedMemorySize, ATTN_SMEM);
    cudaFuncSetAttribute(gemm_mma<0>, cudaFuncAttributeMaxDynamicSharedMemorySize, GEMM_SMEM);
    cudaFuncSetAttribute(gemm_mma<1>, cudaFuncAttributeMaxDynamicSharedMemorySize, GEMM_SMEM);

    // 1) convert x + wqkv (qkv GEMM inputs)
    prep1_kernel<<<8192, 256>>>(x, wqkv);

    // 2) qkv GEMM (fused RoPE + scatter); aux CTAs at y==0 run first
    gemm_mma<1><<<dim3(3 * D_MODEL / 128, MROWS / 128 + 1), 256, GEMM_SMEM>>>(
        ah, bh, nullptr, cosb, sinb, wproj, kxl, vxl, pos,
        MROWS, 3 * D_MODEL, D_MODEL);

    // 3) flash attention -> fp16 y
    attn_kernel<<<dim3(TQ / 128, BATCH * NHEADS), 256, ATTN_SMEM>>>(flag);

    // 4) out = y @ w_proj^T
    gemm_mma<0><<<dim3(D_MODEL / 128, MROWS / 128), 256, GEMM_SMEM>>>(
        yh, bp, out, nullptr, nullptr, nullptr, nullptr, nullptr, nullptr,
        MROWS, D_MODEL, D_MODEL);
}

// round 14
// speedup vs baseline: 1.5482x; 1.0129x over previous
#include <cuda_runtime.h>
#include <cuda_fp16.h>
#include <cstdint>

#define D_MODEL 2048
#define NHEADS  16
#define HD      128
#define BATCH   2
#define TQ      1024
#define XLLEN   1024
#define KVLEN   2048
#define MROWS   (BATCH * TQ)    // 2048

// ---------------- scratch (device globals) ----------------
__device__ __half g_yh [(size_t)MROWS * D_MODEL];
__device__ __half g_qh [(size_t)BATCH * NHEADS * TQ * HD];
__device__ __half g_kh [(size_t)BATCH * NHEADS * KVLEN * HD];
__device__ __half g_vh [(size_t)BATCH * NHEADS * KVLEN * HD];
__device__ __half g_ah [(size_t)MROWS * D_MODEL];
__device__ __half g_bh [(size_t)3 * D_MODEL * D_MODEL];
__device__ __half g_bp [(size_t)D_MODEL * D_MODEL];

// ======================= PTX helpers =======================
__device__ __forceinline__ uint32_t smem_u32(const void* p) {
    uint32_t a;
    asm("{ .reg .u64 t; cvta.to.shared.u64 t, %1; cvt.u32.u64 %0, t; }" : "=r"(a) : "l"(p));
    return a;
}
__device__ __forceinline__ void ldm4(uint32_t* r, uint32_t a) {
    asm volatile("ldmatrix.sync.aligned.m8n8.x4.shared.b16 {%0,%1,%2,%3}, [%4];"
                 : "=r"(r[0]), "=r"(r[1]), "=r"(r[2]), "=r"(r[3]) : "r"(a));
}
__device__ __forceinline__ void ldm4t(uint32_t* r, uint32_t a) {
    asm volatile("ldmatrix.sync.aligned.m8n8.x4.trans.shared.b16 {%0,%1,%2,%3}, [%4];"
                 : "=r"(r[0]), "=r"(r[1]), "=r"(r[2]), "=r"(r[3]) : "r"(a));
}
__device__ __forceinline__ void mma16816(float* d, const uint32_t* a, uint32_t b0, uint32_t b1) {
    asm volatile("mma.sync.aligned.m16n8k16.row.col.f32.f16.f16.f32 "
                 "{%0,%1,%2,%3}, {%4,%5,%6,%7}, {%8,%9}, {%0,%1,%2,%3};"
                 : "+f"(d[0]), "+f"(d[1]), "+f"(d[2]), "+f"(d[3])
                 : "r"(a[0]), "r"(a[1]), "r"(a[2]), "r"(a[3]), "r"(b0), "r"(b1));
}
__device__ __forceinline__ void cpa16(uint32_t dst, const void* src) {
    asm volatile("cp.async.cg.shared.global [%0], [%1], 16;" :: "r"(dst), "l"(src));
}
__device__ __forceinline__ void cpa_commit() { asm volatile("cp.async.commit_group;" ::: "memory"); }
__device__ __forceinline__ void cpa_wait1()  { asm volatile("cp.async.wait_group 1;" ::: "memory"); }
__device__ __forceinline__ void cpa_wait0()  { asm volatile("cp.async.wait_group 0;" ::: "memory"); }
// packed-half exp2: one MUFU op for two values; results are P fragments
__device__ __forceinline__ uint32_t ex2h2(float a, float b) {
    __half2 t = __floats2half2_rn(a, b);
    uint32_t u = *(uint32_t*)&t, r;
    asm("ex2.approx.f16x2 %0, %1;" : "=r"(r) : "r"(u));
    return r;
}
__device__ __forceinline__ uint4 cvt8(float4 a, float4 b) {
    __half h[8] = {__float2half_rn(a.x), __float2half_rn(a.y),
                   __float2half_rn(a.z), __float2half_rn(a.w),
                   __float2half_rn(b.x), __float2half_rn(b.y),
                   __float2half_rn(b.z), __float2half_rn(b.w)};
    return *(uint4*)h;
}

// =====================================================================
// prep1: fp32->fp16 for x + wqkv; 16 elems/thread (4 independent
// float4 loads -> MLP 4) for higher HBM utilization.
// =====================================================================
__global__ void prep1_kernel(const float* __restrict__ x, const float* __restrict__ wqkv)
{
    const int blk = blockIdx.x;       // 4096 blocks
    const float* src; __half* dst; int i;
    if (blk < 1024) { src = x;    dst = g_ah; i = blk * 256 + threadIdx.x; }
    else            { src = wqkv; dst = g_bh; i = (blk - 1024) * 256 + threadIdx.x; }
    float4 v0 = ((const float4*)src)[4 * i];
    float4 v1 = ((const float4*)src)[4 * i + 1];
    float4 v2 = ((const float4*)src)[4 * i + 2];
    float4 v3 = ((const float4*)src)[4 * i + 3];
    *(uint4*)(dst + (size_t)i * 16)     = cvt8(v0, v1);
    *(uint4*)(dst + (size_t)i * 16 + 8) = cvt8(v2, v3);
}

// =====================================================================
// fp16 mma.sync NT GEMM (R13 verbatim): 128x128 CTA tile, BK=32,
// 8 warps (64x32), 4-stage cp.async ring, ONE barrier per K-block.
// MODE 0: fp32 C.  MODE 1: fused RoPE + scatter; y==0 = aux workers.
// =====================================================================
#define GTILE_B  10240            // 128 rows x 80B
#define GSTG_B   (2 * GTILE_B)    // A + B
#define GEMM_SMEM (4 * GSTG_B)    // 81920

#define AUX_NW   (D_MODEL * D_MODEL / 8)               // wproj units
#define AUX_NX   (BATCH * XLLEN * D_MODEL / 8)         // XL units
#define AUX_THREADS (48 * 256)

template<int MODE>
__global__ __launch_bounds__(256, 2) void gemm_mma(
    const __half* __restrict__ A, const __half* __restrict__ B,
    float* __restrict__ C, const float* __restrict__ cosb, const float* __restrict__ sinb,
    const float* __restrict__ wproj, const float* __restrict__ kxl,
    const float* __restrict__ vxl, const float* __restrict__ pos,
    int M, int N, int K)
{
    if (MODE == 1 && blockIdx.y == 0) {
        int tg = blockIdx.x * 256 + threadIdx.x;
        for (int u = tg; u < AUX_NW + AUX_NX; u += AUX_THREADS) {
            if (u < AUX_NW) {
                float4 v0 = ((const float4*)wproj)[2 * u];
                float4 v1 = ((const float4*)wproj)[2 * u + 1];
                *(uint4*)(g_bp + (size_t)u * 8) = cvt8(v0, v1);
            } else {
                int idx = u - AUX_NW;                // (b, t, h, d8)
                int d8 = idx & 15;
                int h  = (idx >> 4) & 15;
                int t  = (idx >> 8) & 1023;
                int b  = idx >> 18;
                size_t src = ((size_t)(b * XLLEN + t)) * D_MODEL + h * HD + d8 * 8;
                size_t ps  = (size_t)t * D_MODEL + h * HD + d8 * 8;
                float4 k0 = *(const float4*)(kxl + src), k1 = *(const float4*)(kxl + src + 4);
                float4 p0 = *(const float4*)(pos + ps),  p1 = *(const float4*)(pos + ps + 4);
                float4 v0 = *(const float4*)(vxl + src), v1 = *(const float4*)(vxl + src + 4);
                k0.x += p0.x; k0.y += p0.y; k0.z += p0.z; k0.w += p0.w;
                k1.x += p1.x; k1.y += p1.y; k1.z += p1.z; k1.w += p1.w;
                size_t dst = ((size_t)((b * NHEADS + h) * KVLEN + t)) * HD + d8 * 8;
                *(uint4*)&g_kh[dst] = cvt8(k0, k1);
                *(uint4*)&g_vh[dst] = cvt8(v0, v1);
            }
        }
        return;
    }

    extern __shared__ __align__(16) char smraw[];
    const uint32_t sb = smem_u32(smraw);
    const int tid = threadIdx.x, wid = tid >> 5, lane = tid & 31;
    const int wm = wid & 1, wn = wid >> 1;
    const int myrow = (MODE == 1) ? ((int)blockIdx.y - 1) : (int)blockIdx.y;
    const int mb = myrow * 128, nb = blockIdx.x * 128;

    const __half* Asrc = A + (size_t)mb * K;
    const __half* Bsrc = B + (size_t)nb * K;
    const int NKB = K >> 5;
    const int lrow = tid >> 2, lkc = (tid & 3);

#pragma unroll
    for (int s = 0; s < 2; s++) {
        const uint32_t st = sb + s * GSTG_B;
        const int ko = s * 32;
#pragma unroll
        for (int i = 0; i < 2; i++) {
            int row = lrow + i * 64;
            cpa16(st + row * 80 + lkc * 16, Asrc + (size_t)row * K + ko + lkc * 8);
            cpa16(st + GTILE_B + row * 80 + lkc * 16, Bsrc + (size_t)row * K + ko + lkc * 8);
        }
        cpa_commit();
    }

    float acc[4][4][4];
#pragma unroll
    for (int a = 0; a < 4; a++)
#pragma unroll
        for (int b = 0; b < 4; b++)
#pragma unroll
            for (int e = 0; e < 4; e++) acc[a][b][e] = 0.f;

    const uint32_t arow = (uint32_t)(wm * 64 + (lane & 15)) * 80;
    const uint32_t brow = (uint32_t)(wn * 32 + (lane & 15)) * 80;
    const uint32_t lhalf = (lane >> 4) * 16;

    for (int kb = 0; kb < NKB; kb++) {
        if (kb + 2 < NKB) cpa_wait1(); else cpa_wait0();
        __syncthreads();
        const uint32_t st = sb + (kb & 3) * GSTG_B;

        uint32_t Af[4][4], Bf[2][4];
#pragma unroll
        for (int mt = 0; mt < 4; mt++)
            ldm4(Af[mt], st + arow + mt * 16 * 80 + lhalf);
#pragma unroll
        for (int np = 0; np < 2; np++)
            ldm4(Bf[np], st + GTILE_B + brow + np * 16 * 80 + lhalf);

        if (kb + 2 < NKB) {
            const uint32_t pst = sb + ((kb + 2) & 3) * GSTG_B;
            const int ko = (kb + 2) * 32;
#pragma unroll
            for (int i = 0; i < 2; i++) {
                int row = lrow + i * 64;
                cpa16(pst + row * 80 + lkc * 16, Asrc + (size_t)row * K + ko + lkc * 8);
                cpa16(pst + GTILE_B + row * 80 + lkc * 16, Bsrc + (size_t)row * K + ko + lkc * 8);
            }
            cpa_commit();
        }

#pragma unroll
        for (int mt = 0; mt < 4; mt++)
#pragma unroll
            for (int nt = 0; nt < 4; nt++)
                mma16816(acc[mt][nt], Af[mt], Bf[nt >> 1][nt & 1], Bf[nt >> 1][(nt & 1) + 2]);

#pragma unroll
        for (int mt = 0; mt < 4; mt++)
            ldm4(Af[mt], st + arow + mt * 16 * 80 + 32 + lhalf);
#pragma unroll
        for (int np = 0; np < 2; np++)
            ldm4(Bf[np], st + GTILE_B + brow + np * 16 * 80 + 32 + lhalf);
#pragma unroll
        for (int mt = 0; mt < 4; mt++)
#pragma unroll
            for (int nt = 0; nt < 4; nt++)
                mma16816(acc[mt][nt], Af[mt], Bf[nt >> 1][nt & 1], Bf[nt >> 1][(nt & 1) + 2]);
    }

    if (MODE == 0) {
#pragma unroll
        for (int mt = 0; mt < 4; mt++) {
            int row0 = mb + wm * 64 + mt * 16 + (lane >> 2);
#pragma unroll
            for (int nt = 0; nt < 4; nt++) {
                int col = nb + wn * 32 + nt * 8 + (lane & 3) * 2;
                *(float2*)&C[(size_t)row0 * N + col]       = make_float2(acc[mt][nt][0], acc[mt][nt][1]);
                *(float2*)&C[(size_t)(row0 + 8) * N + col] = make_float2(acc[mt][nt][2], acc[mt][nt][3]);
            }
        }
    } else {
        const int region = nb >> 11;
        const int hh = (nb & 2047) >> 7;
#pragma unroll
        for (int mt = 0; mt < 4; mt++) {
#pragma unroll
            for (int i = 0; i < 2; i++) {
                int row = mb + wm * 64 + mt * 16 + (lane >> 2) + i * 8;
                int bb = row >> 10, t = row & 1023;
#pragma unroll
                for (int nt = 0; nt < 4; nt++) {
                    int d = wn * 32 + nt * 8 + (lane & 3) * 2;
                    float a0 = acc[mt][nt][2 * i], a1 = acc[mt][nt][2 * i + 1];
                    if (region == 2) {
                        size_t dst = ((size_t)(bb * NHEADS + hh) * KVLEN + XLLEN + t) * HD + d;
                        *(__half2*)&g_vh[dst] = __floats2half2_rn(a0, a1);
                    } else {
                        int dp = d >> 1;
                        float cv = cosb[t * 64 + dp], sv = sinb[t * 64 + dp];
                        float o0 = a0 * cv - a1 * sv;
                        float o1 = a0 * sv + a1 * cv;
                        if (region == 0) {
                            size_t dst = ((size_t)(bb * NHEADS + hh) * TQ + t) * HD + d;
                            *(__half2*)&g_qh[dst] = __floats2half2_rn(o0, o1);
                        } else {
                            size_t dst = ((size_t)(bb * NHEADS + hh) * KVLEN + XLLEN + t) * HD + d;
                            *(__half2*)&g_kh[dst] = __floats2half2_rn(o0, o1);
                        }
                    }
                }
            }
        }
    }
}

// =====================================================================
// Flash attention: BQ=128, BK=64, D=128, 8 warps, 2-stage KV,
// 2 CTAs/SM (104.4KB smem, <=128 regs; Q frags reloaded from smem).
// ONE barrier per tile; ex2.approx.f16x2 softmax; P from S regs.
// grid (8, 32) = 256 CTAs over 296 slots -> ONE wave.
// =====================================================================
#define AQSZ   34816                      // 128 rows x 272B
#define AKV    AQSZ
#define AKVSTG 34816                      // K(64x272) + V(64x272)
#define AVOF   17408
#define ATTN_SMEM (AQSZ + 2 * AKVSTG)     // 104448

__global__ __launch_bounds__(256, 2) void attn_kernel(const int* __restrict__ flag)
{
    extern __shared__ __align__(16) char smraw[];
    const uint32_t sb = smem_u32(smraw);
    const int tid = threadIdx.x, w = tid >> 5, lane = tid & 31;
    const int qt = blockIdx.x, bh = blockIdx.y;
    const int b = bh >> 4, h = bh & 15;
    const int qbase = qt * 128;
    const int causal = *flag;

    const __half* Qh = g_qh + (size_t)bh * (TQ * HD);
    const __half* Kh = g_kh + (size_t)bh * (KVLEN * HD);
    const __half* Vh = g_vh + (size_t)bh * (KVLEN * HD);

    int ntile = causal ? (2 * qt + 18) : 32;
    if (ntile > 32) ntile = 32;

    // Q tile + KV tile 0
#pragma unroll
    for (int i = 0; i < 8; i++) {
        int c = tid + i * 256;
        int row = c >> 4, kc = c & 15;
        cpa16(sb + row * 272 + kc * 16, Qh + (size_t)(qbase + row) * HD + kc * 8);
    }
    cpa_commit();
#pragma unroll
    for (int i = 0; i < 4; i++) {
        int c = tid + i * 256;
        int row = c >> 4, kc = c & 15;
        cpa16(sb + AKV + row * 272 + kc * 16, Kh + (size_t)row * HD + kc * 8);
        cpa16(sb + AKV + AVOF + row * 272 + kc * 16, Vh + (size_t)row * HD + kc * 8);
    }
    cpa_commit();

    float oacc[16][4];
#pragma unroll
    for (int nq = 0; nq < 16; nq++)
#pragma unroll
        for (int e = 0; e < 4; e++) oacc[nq][e] = 0.f;
    float mrow[2] = {-1e30f, -1e30f}, lrow[2] = {0.f, 0.f};

    const float scale2 = 0.12751879523525493f;   // log2(e)/sqrt(128)
    const int roff = KVLEN - TQ;
    const uint32_t qrow = (uint32_t)(w * 16 + (lane & 15)) * 272;
    const uint32_t krow = (uint32_t)(lane & 15) * 272;
    const uint32_t lhalf = (lane >> 4) * 16;

    for (int kt = 0; kt < ntile; kt++) {
        cpa_wait0();                              // tile kt (and Q) arrived
        __syncthreads();                          // + all warps done reading kt-1
        const uint32_t kvst = sb + AKV + (kt & 1) * AKVSTG;

        if (kt + 1 < ntile) {                     // prefetch kt+1 into retired buf
            const uint32_t st = sb + AKV + ((kt + 1) & 1) * AKVSTG;
            const int kb0 = (kt + 1) * 64;
#pragma unroll
            for (int i = 0; i < 4; i++) {
                int c = tid + i * 256;
                int row = c >> 4, kc = c & 15;
                cpa16(st + row * 272 + kc * 16, Kh + (size_t)(kb0 + row) * HD + kc * 8);
                cpa16(st + AVOF + row * 272 + kc * 16, Vh + (size_t)(kb0 + row) * HD + kc * 8);
            }
            cpa_commit();
        }

        // ---- S = Q K^T (Q fragments reloaded from smem: saves 32 regs) ----
        float sacc[8][4];
#pragma unroll
        for (int nt = 0; nt < 8; nt++)
#pragma unroll
            for (int e = 0; e < 4; e++) sacc[nt][e] = 0.f;

#pragma unroll
        for (int ks = 0; ks < 8; ks++) {
            const uint32_t koff = ks * 32 + lhalf;
            uint32_t qf[4];
            ldm4(qf, sb + qrow + koff);
#pragma unroll
            for (int np = 0; np < 4; np++) {
                uint32_t kf[4];
                ldm4(kf, kvst + krow + np * 16 * 272 + koff);
                mma16816(sacc[2 * np],     qf, kf[0], kf[2]);
                mma16816(sacc[2 * np + 1], qf, kf[1], kf[3]);
            }
        }

        // ---- scale (log2 domain); causal mask under uniform branch ----
#pragma unroll
        for (int nt = 0; nt < 8; nt++)
#pragma unroll
            for (int e = 0; e < 4; e++) sacc[nt][e] *= scale2;
        if (causal) {
            const int kbase = kt * 64;
            const int rglo = qbase + w * 16 + (lane >> 2) + roff;
#pragma unroll
            for (int nt = 0; nt < 8; nt++)
#pragma unroll
                for (int e = 0; e < 4; e++) {
                    int cl = kbase + nt * 8 + (lane & 3) * 2 + (e & 1);
                    if (cl > rglo + (e >> 1) * 8) sacc[nt][e] = -1e30f;
                }
        }

        // ---- register softmax (quad shfl) ----
        float ml[2] = {-1e30f, -1e30f};
#pragma unroll
        for (int nt = 0; nt < 8; nt++) {
            ml[0] = fmaxf(ml[0], fmaxf(sacc[nt][0], sacc[nt][1]));
            ml[1] = fmaxf(ml[1], fmaxf(sacc[nt][2], sacc[nt][3]));
        }
#pragma unroll
        for (int i = 0; i < 2; i++) {
            ml[i] = fmaxf(ml[i], __shfl_xor_sync(0xffffffffu, ml[i], 1));
            ml[i] = fmaxf(ml[i], __shfl_xor_sync(0xffffffffu, ml[i], 2));
        }
        float mn[2], al[2];
#pragma unroll
        for (int i = 0; i < 2; i++) {
            mn[i] = fmaxf(mrow[i], ml[i]);
            al[i] = exp2f(mrow[i] - mn[i]);
            mrow[i] = mn[i];
        }

        // ---- P = exp2(S - m) packed fp16; directly PV A-fragments ----
        float ls[2] = {0.f, 0.f};
        uint32_t pf[4][4];
#pragma unroll
        for (int nt = 0; nt < 8; nt++) {
            uint32_t p01 = ex2h2(sacc[nt][0] - mn[0], sacc[nt][1] - mn[0]);
            uint32_t p23 = ex2h2(sacc[nt][2] - mn[1], sacc[nt][3] - mn[1]);
            pf[nt >> 1][(nt & 1) * 2 + 0] = p01;
            pf[nt >> 1][(nt & 1) * 2 + 1] = p23;
            float2 f0 = __half22float2(*(__half2*)&p01);
            float2 f1 = __half22float2(*(__half2*)&p23);
            ls[0] += f0.x + f0.y;
            ls[1] += f1.x + f1.y;
        }
#pragma unroll
        for (int i = 0; i < 2; i++) {
            ls[i] += __shfl_xor_sync(0xffffffffu, ls[i], 1);
            ls[i] += __shfl_xor_sync(0xffffffffu, ls[i], 2);
            lrow[i] = lrow[i] * al[i] + ls[i];
        }
#pragma unroll
        for (int nq = 0; nq < 16; nq++) {
            oacc[nq][0] *= al[0]; oacc[nq][1] *= al[0];
            oacc[nq][2] *= al[1]; oacc[nq][3] *= al[1];
        }

        // ---- O += P V ----
#pragma unroll
        for (int kp = 0; kp < 4; kp++) {
            const uint32_t vrow = (uint32_t)(kp * 16 + (lane & 15)) * 272 + lhalf;
#pragma unroll
            for (int np = 0; np < 8; np++) {
                uint32_t vb[4];
                ldm4t(vb, kvst + AVOF + vrow + np * 32);
                mma16816(oacc[2 * np],     pf[kp], vb[0], vb[1]);
                mma16816(oacc[2 * np + 1], pf[kp], vb[2], vb[3]);
            }
        }
    }

    // ---- epilogue: O / l -> fp16 y ----
#pragma unroll
    for (int i = 0; i < 2; i++) {
        float inv = 1.0f / lrow[i];
        int rl = w * 16 + (lane >> 2) + i * 8;
        __half* Yp = g_yh + (size_t)(b * TQ + qbase + rl) * D_MODEL + h * HD;
#pragma unroll
        for (int nq = 0; nq < 16; nq++) {
            int col = nq * 8 + (lane & 3) * 2;
            *(__half2*)(Yp + col) =
                __floats2half2_rn(oacc[nq][2 * i] * inv, oacc[nq][2 * i + 1] * inv);
        }
    }
}

// =====================================================================
// launch
// =====================================================================
extern "C" void kernel_launch(void* const* d_in, const int* in_sizes, int n_in,
                              void* d_out, int out_size)
{
    const float* x     = (const float*)d_in[0];
    const float* cosb  = (const float*)d_in[1];
    const float* sinb  = (const float*)d_in[2];
    const float* kxl   = (const float*)d_in[3];
    const float* vxl   = (const float*)d_in[4];
    const float* pos   = (const float*)d_in[5];
    const float* wqkv  = (const float*)d_in[6];
    const float* wproj = (const float*)d_in[7];
    const int*   flag  = (const int*)d_in[8];
    float*       out   = (float*)d_out;

    __half *ah, *bh, *bp, *yh;
    cudaGetSymbolAddress((void**)&ah, g_ah);
    cudaGetSymbolAddress((void**)&bh, g_bh);
    cudaGetSymbolAddress((void**)&bp, g_bp);
    cudaGetSymbolAddress((void**)&yh, g_yh);

    cudaFuncSetAttribute(attn_kernel, cudaFuncAttributeMaxDynamicSharedMemorySize, ATTN_SMEM);
    cudaFuncSetAttribute(gemm_mma<0>, cudaFuncAttributeMaxDynamicSharedMemorySize, GEMM_SMEM);
    cudaFuncSetAttribute(gemm_mma<1>, cudaFuncAttributeMaxDynamicSharedMemorySize, GEMM_SMEM);

    // 1) convert x + wqkv (qkv GEMM inputs)
    prep1_kernel<<<4096, 256>>>(x, wqkv);

    // 2) qkv GEMM (fused RoPE + scatter); aux CTAs at y==0 run first
    gemm_mma<1><<<dim3(3 * D_MODEL / 128, MROWS / 128 + 1), 256, GEMM_SMEM>>>(
        ah, bh, nullptr, cosb, sinb, wproj, kxl, vxl, pos,
        MROWS, 3 * D_MODEL, D_MODEL);

    // 3) flash attention -> fp16 y (one wave: 256 CTAs, 2/SM)
    attn_kernel<<<dim3(TQ / 128, BATCH * NHEADS), 256, ATTN_SMEM>>>(flag);

    // 4) out = y @ w_proj^T
    gemm_mma<0><<<dim3(D_MODEL / 128, MROWS / 128), 256, GEMM_SMEM>>>(
        yh, bp, out, nullptr, nullptr, nullptr, nullptr, nullptr, nullptr,
        MROWS, D_MODEL, D_MODEL);
}

// round 15
// speedup vs baseline: 1.5660x; 1.0115x over previous
#include <cuda_runtime.h>
#include <cuda_fp16.h>
#include <cstdint>

#define D_MODEL 2048
#define NHEADS  16
#define HD      128
#define BATCH   2
#define TQ      1024
#define XLLEN   1024
#define KVLEN   2048
#define MROWS   (BATCH * TQ)    // 2048

// ---------------- scratch (device globals) ----------------
__device__ __half g_yh [(size_t)MROWS * D_MODEL];
__device__ __half g_qh [(size_t)BATCH * NHEADS * TQ * HD];
__device__ __half g_kh [(size_t)BATCH * NHEADS * KVLEN * HD];
__device__ __half g_vh [(size_t)BATCH * NHEADS * KVLEN * HD];
__device__ __half g_ah [(size_t)MROWS * D_MODEL];
__device__ __half g_bh [(size_t)3 * D_MODEL * D_MODEL];
__device__ __half g_bp [(size_t)D_MODEL * D_MODEL];

// ======================= PTX helpers =======================
__device__ __forceinline__ uint32_t smem_u32(const void* p) {
    uint32_t a;
    asm("{ .reg .u64 t; cvta.to.shared.u64 t, %1; cvt.u32.u64 %0, t; }" : "=r"(a) : "l"(p));
    return a;
}
__device__ __forceinline__ void ldm4(uint32_t* r, uint32_t a) {
    asm volatile("ldmatrix.sync.aligned.m8n8.x4.shared.b16 {%0,%1,%2,%3}, [%4];"
                 : "=r"(r[0]), "=r"(r[1]), "=r"(r[2]), "=r"(r[3]) : "r"(a));
}
__device__ __forceinline__ void ldm4t(uint32_t* r, uint32_t a) {
    asm volatile("ldmatrix.sync.aligned.m8n8.x4.trans.shared.b16 {%0,%1,%2,%3}, [%4];"
                 : "=r"(r[0]), "=r"(r[1]), "=r"(r[2]), "=r"(r[3]) : "r"(a));
}
__device__ __forceinline__ void mma16816(float* d, const uint32_t* a, uint32_t b0, uint32_t b1) {
    asm volatile("mma.sync.aligned.m16n8k16.row.col.f32.f16.f16.f32 "
                 "{%0,%1,%2,%3}, {%4,%5,%6,%7}, {%8,%9}, {%0,%1,%2,%3};"
                 : "+f"(d[0]), "+f"(d[1]), "+f"(d[2]), "+f"(d[3])
                 : "r"(a[0]), "r"(a[1]), "r"(a[2]), "r"(a[3]), "r"(b0), "r"(b1));
}
__device__ __forceinline__ void cpa16(uint32_t dst, const void* src) {
    asm volatile("cp.async.cg.shared.global [%0], [%1], 16;" :: "r"(dst), "l"(src));
}
__device__ __forceinline__ void cpa_commit() { asm volatile("cp.async.commit_group;" ::: "memory"); }
__device__ __forceinline__ void cpa_wait1()  { asm volatile("cp.async.wait_group 1;" ::: "memory"); }
__device__ __forceinline__ void cpa_wait0()  { asm volatile("cp.async.wait_group 0;" ::: "memory"); }
// packed-half exp2: one MUFU op for two values; results are P fragments
__device__ __forceinline__ uint32_t ex2h2(float a, float b) {
    __half2 t = __floats2half2_rn(a, b);
    uint32_t u = *(uint32_t*)&t, r;
    asm("ex2.approx.f16x2 %0, %1;" : "=r"(r) : "r"(u));
    return r;
}
__device__ __forceinline__ uint4 cvt8(float4 a, float4 b) {
    __half h[8] = {__float2half_rn(a.x), __float2half_rn(a.y),
                   __float2half_rn(a.z), __float2half_rn(a.w),
                   __float2half_rn(b.x), __float2half_rn(b.y),
                   __float2half_rn(b.z), __float2half_rn(b.w)};
    return *(uint4*)h;
}

// =====================================================================
// prep1: fp32->fp16 for x + wqkv; 16 elems/thread (MLP 4)
// =====================================================================
__global__ void prep1_kernel(const float* __restrict__ x, const float* __restrict__ wqkv)
{
    const int blk = blockIdx.x;       // 4096 blocks
    const float* src; __half* dst; int i;
    if (blk < 1024) { src = x;    dst = g_ah; i = blk * 256 + threadIdx.x; }
    else            { src = wqkv; dst = g_bh; i = (blk - 1024) * 256 + threadIdx.x; }
    float4 v0 = ((const float4*)src)[4 * i];
    float4 v1 = ((const float4*)src)[4 * i + 1];
    float4 v2 = ((const float4*)src)[4 * i + 2];
    float4 v3 = ((const float4*)src)[4 * i + 3];
    *(uint4*)(dst + (size_t)i * 16)     = cvt8(v0, v1);
    *(uint4*)(dst + (size_t)i * 16 + 8) = cvt8(v2, v3);
}

// =====================================================================
// fp16 mma.sync NT GEMM: 128x128 CTA tile, BK=64, 8 warps (64x32),
// 2-stage ring, attn-style prefetch-after-barrier (distance 1),
// ONE barrier + one wait per 128 mma.  Rows 176B stride
// (conflict-free ldmatrix: banks 44r mod 32 all distinct).
// MODE 0: fp32 C.  MODE 1: fused RoPE + scatter; y==0 = aux workers.
// =====================================================================
#define GTILE_B  22528            // 128 rows x 176B
#define GSTG_B   (2 * GTILE_B)    // A + B = 45056
#define GEMM_SMEM (2 * GSTG_B)    // 90112

#define AUX_NW   (D_MODEL * D_MODEL / 8)               // wproj units
#define AUX_NX   (BATCH * XLLEN * D_MODEL / 8)         // XL units
#define AUX_THREADS (48 * 256)

template<int MODE>
__global__ __launch_bounds__(256, 2) void gemm_mma(
    const __half* __restrict__ A, const __half* __restrict__ B,
    float* __restrict__ C, const float* __restrict__ cosb, const float* __restrict__ sinb,
    const float* __restrict__ wproj, const float* __restrict__ kxl,
    const float* __restrict__ vxl, const float* __restrict__ pos,
    int M, int N, int K)
{
    if (MODE == 1 && blockIdx.y == 0) {
        int tg = blockIdx.x * 256 + threadIdx.x;
        for (int u = tg; u < AUX_NW + AUX_NX; u += AUX_THREADS) {
            if (u < AUX_NW) {
                float4 v0 = ((const float4*)wproj)[2 * u];
                float4 v1 = ((const float4*)wproj)[2 * u + 1];
                *(uint4*)(g_bp + (size_t)u * 8) = cvt8(v0, v1);
            } else {
                int idx = u - AUX_NW;                // (b, t, h, d8)
                int d8 = idx & 15;
                int h  = (idx >> 4) & 15;
                int t  = (idx >> 8) & 1023;
                int b  = idx >> 18;
                size_t src = ((size_t)(b * XLLEN + t)) * D_MODEL + h * HD + d8 * 8;
                size_t ps  = (size_t)t * D_MODEL + h * HD + d8 * 8;
                float4 k0 = *(const float4*)(kxl + src), k1 = *(const float4*)(kxl + src + 4);
                float4 p0 = *(const float4*)(pos + ps),  p1 = *(const float4*)(pos + ps + 4);
                float4 v0 = *(const float4*)(vxl + src), v1 = *(const float4*)(vxl + src + 4);
                k0.x += p0.x; k0.y += p0.y; k0.z += p0.z; k0.w += p0.w;
                k1.x += p1.x; k1.y += p1.y; k1.z += p1.z; k1.w += p1.w;
                size_t dst = ((size_t)((b * NHEADS + h) * KVLEN + t)) * HD + d8 * 8;
                *(uint4*)&g_kh[dst] = cvt8(k0, k1);
                *(uint4*)&g_vh[dst] = cvt8(v0, v1);
            }
        }
        return;
    }

    extern __shared__ __align__(16) char smraw[];
    const uint32_t sb = smem_u32(smraw);
    const int tid = threadIdx.x, wid = tid >> 5, lane = tid & 31;
    const int wm = wid & 1, wn = wid >> 1;
    const int myrow = (MODE == 1) ? ((int)blockIdx.y - 1) : (int)blockIdx.y;
    const int mb = myrow * 128, nb = blockIdx.x * 128;

    const __half* Asrc = A + (size_t)mb * K;
    const __half* Bsrc = B + (size_t)nb * K;
    const int NKB = K >> 6;                 // BK = 64
    const int lrow = tid >> 3, lkc = tid & 7;   // 32 rows x 8 chunks per 256-thr pass

    // prologue: stage 0 only (distance-1 prefetch pattern)
    {
        const uint32_t st = sb;
#pragma unroll
        for (int i = 0; i < 4; i++) {
            int row = lrow + i * 32;
            cpa16(st + row * 176 + lkc * 16, Asrc + (size_t)row * K + lkc * 8);
            cpa16(st + GTILE_B + row * 176 + lkc * 16, Bsrc + (size_t)row * K + lkc * 8);
        }
        cpa_commit();
    }

    float acc[4][4][4];
#pragma unroll
    for (int a = 0; a < 4; a++)
#pragma unroll
        for (int b = 0; b < 4; b++)
#pragma unroll
            for (int e = 0; e < 4; e++) acc[a][b][e] = 0.f;

    const uint32_t arow = (uint32_t)(wm * 64 + (lane & 15)) * 176;
    const uint32_t brow = (uint32_t)(wn * 32 + (lane & 15)) * 176;
    const uint32_t lhalf = (lane >> 4) * 16;

    for (int kb = 0; kb < NKB; kb++) {
        cpa_wait0();                                   // block kb arrived
        __syncthreads();                               // all reads of kb-1 done
        const uint32_t st = sb + (kb & 1) * GSTG_B;

        if (kb + 1 < NKB) {                            // prefetch kb+1 into retired buf
            const uint32_t pst = sb + ((kb + 1) & 1) * GSTG_B;
            const int ko = (kb + 1) * 64;
#pragma unroll
            for (int i = 0; i < 4; i++) {
                int row = lrow + i * 32;
                cpa16(pst + row * 176 + lkc * 16, Asrc + (size_t)row * K + ko + lkc * 8);
                cpa16(pst + GTILE_B + row * 176 + lkc * 16, Bsrc + (size_t)row * K + ko + lkc * 8);
            }
            cpa_commit();
        }

        // ---- 4 k-steps of 16, 128 mma per barrier ----
#pragma unroll
        for (int ks = 0; ks < 4; ks++) {
            const uint32_t koff = ks * 32 + lhalf;
            uint32_t Af[4][4], Bf[2][4];
#pragma unroll
            for (int mt = 0; mt < 4; mt++)
                ldm4(Af[mt], st + arow + mt * 16 * 176 + koff);
#pragma unroll
            for (int np = 0; np < 2; np++)
                ldm4(Bf[np], st + GTILE_B + brow + np * 16 * 176 + koff);
#pragma unroll
            for (int mt = 0; mt < 4; mt++)
#pragma unroll
                for (int nt = 0; nt < 4; nt++)
                    mma16816(acc[mt][nt], Af[mt], Bf[nt >> 1][nt & 1], Bf[nt >> 1][(nt & 1) + 2]);
        }
    }

    if (MODE == 0) {
#pragma unroll
        for (int mt = 0; mt < 4; mt++) {
            int row0 = mb + wm * 64 + mt * 16 + (lane >> 2);
#pragma unroll
            for (int nt = 0; nt < 4; nt++) {
                int col = nb + wn * 32 + nt * 8 + (lane & 3) * 2;
                *(float2*)&C[(size_t)row0 * N + col]       = make_float2(acc[mt][nt][0], acc[mt][nt][1]);
                *(float2*)&C[(size_t)(row0 + 8) * N + col] = make_float2(acc[mt][nt][2], acc[mt][nt][3]);
            }
        }
    } else {
        const int region = nb >> 11;
        const int hh = (nb & 2047) >> 7;
#pragma unroll
        for (int mt = 0; mt < 4; mt++) {
#pragma unroll
            for (int i = 0; i < 2; i++) {
                int row = mb + wm * 64 + mt * 16 + (lane >> 2) + i * 8;
                int bb = row >> 10, t = row & 1023;
#pragma unroll
                for (int nt = 0; nt < 4; nt++) {
                    int d = wn * 32 + nt * 8 + (lane & 3) * 2;
                    float a0 = acc[mt][nt][2 * i], a1 = acc[mt][nt][2 * i + 1];
                    if (region == 2) {
                        size_t dst = ((size_t)(bb * NHEADS + hh) * KVLEN + XLLEN + t) * HD + d;
                        *(__half2*)&g_vh[dst] = __floats2half2_rn(a0, a1);
                    } else {
                        int dp = d >> 1;
                        float cv = cosb[t * 64 + dp], sv = sinb[t * 64 + dp];
                        float o0 = a0 * cv - a1 * sv;
                        float o1 = a0 * sv + a1 * cv;
                        if (region == 0) {
                            size_t dst = ((size_t)(bb * NHEADS + hh) * TQ + t) * HD + d;
                            *(__half2*)&g_qh[dst] = __floats2half2_rn(o0, o1);
                        } else {
                            size_t dst = ((size_t)(bb * NHEADS + hh) * KVLEN + XLLEN + t) * HD + d;
                            *(__half2*)&g_kh[dst] = __floats2half2_rn(o0, o1);
                        }
                    }
                }
            }
        }
    }
}

// =====================================================================
// Flash attention (R14 verbatim): BQ=128, BK=64, D=128, 8 warps,
// 2-stage KV, 2 CTAs/SM, ONE barrier per tile, ex2.approx softmax.
// =====================================================================
#define AQSZ   34816                      // 128 rows x 272B
#define AKV    AQSZ
#define AKVSTG 34816                      // K(64x272) + V(64x272)
#define AVOF   17408
#define ATTN_SMEM (AQSZ + 2 * AKVSTG)     // 104448

__global__ __launch_bounds__(256, 2) void attn_kernel(const int* __restrict__ flag)
{
    extern __shared__ __align__(16) char smraw[];
    const uint32_t sb = smem_u32(smraw);
    const int tid = threadIdx.x, w = tid >> 5, lane = tid & 31;
    const int qt = blockIdx.x, bh = blockIdx.y;
    const int b = bh >> 4, h = bh & 15;
    const int qbase = qt * 128;
    const int causal = *flag;

    const __half* Qh = g_qh + (size_t)bh * (TQ * HD);
    const __half* Kh = g_kh + (size_t)bh * (KVLEN * HD);
    const __half* Vh = g_vh + (size_t)bh * (KVLEN * HD);

    int ntile = causal ? (2 * qt + 18) : 32;
    if (ntile > 32) ntile = 32;

#pragma unroll
    for (int i = 0; i < 8; i++) {
        int c = tid + i * 256;
        int row = c >> 4, kc = c & 15;
        cpa16(sb + row * 272 + kc * 16, Qh + (size_t)(qbase + row) * HD + kc * 8);
    }
    cpa_commit();
#pragma unroll
    for (int i = 0; i < 4; i++) {
        int c = tid + i * 256;
        int row = c >> 4, kc = c & 15;
        cpa16(sb + AKV + row * 272 + kc * 16, Kh + (size_t)row * HD + kc * 8);
        cpa16(sb + AKV + AVOF + row * 272 + kc * 16, Vh + (size_t)row * HD + kc * 8);
    }
    cpa_commit();

    float oacc[16][4];
#pragma unroll
    for (int nq = 0; nq < 16; nq++)
#pragma unroll
        for (int e = 0; e < 4; e++) oacc[nq][e] = 0.f;
    float mrow[2] = {-1e30f, -1e30f}, lrow[2] = {0.f, 0.f};

    const float scale2 = 0.12751879523525493f;   // log2(e)/sqrt(128)
    const int roff = KVLEN - TQ;
    const uint32_t qrow = (uint32_t)(w * 16 + (lane & 15)) * 272;
    const uint32_t krow = (uint32_t)(lane & 15) * 272;
    const uint32_t lhalf = (lane >> 4) * 16;

    for (int kt = 0; kt < ntile; kt++) {
        cpa_wait0();
        __syncthreads();
        const uint32_t kvst = sb + AKV + (kt & 1) * AKVSTG;

        if (kt + 1 < ntile) {
            const uint32_t st = sb + AKV + ((kt + 1) & 1) * AKVSTG;
            const int kb0 = (kt + 1) * 64;
#pragma unroll
            for (int i = 0; i < 4; i++) {
                int c = tid + i * 256;
                int row = c >> 4, kc = c & 15;
                cpa16(st + row * 272 + kc * 16, Kh + (size_t)(kb0 + row) * HD + kc * 8);
                cpa16(st + AVOF + row * 272 + kc * 16, Vh + (size_t)(kb0 + row) * HD + kc * 8);
            }
            cpa_commit();
        }

        float sacc[8][4];
#pragma unroll
        for (int nt = 0; nt < 8; nt++)
#pragma unroll
            for (int e = 0; e < 4; e++) sacc[nt][e] = 0.f;

#pragma unroll
        for (int ks = 0; ks < 8; ks++) {
            const uint32_t koff = ks * 32 + lhalf;
            uint32_t qf[4];
            ldm4(qf, sb + qrow + koff);
#pragma unroll
            for (int np = 0; np < 4; np++) {
                uint32_t kf[4];
                ldm4(kf, kvst + krow + np * 16 * 272 + koff);
                mma16816(sacc[2 * np],     qf, kf[0], kf[2]);
                mma16816(sacc[2 * np + 1], qf, kf[1], kf[3]);
            }
        }

#pragma unroll
        for (int nt = 0; nt < 8; nt++)
#pragma unroll
            for (int e = 0; e < 4; e++) sacc[nt][e] *= scale2;
        if (causal) {
            const int kbase = kt * 64;
            const int rglo = qbase + w * 16 + (lane >> 2) + roff;
#pragma unroll
            for (int nt = 0; nt < 8; nt++)
#pragma unroll
                for (int e = 0; e < 4; e++) {
                    int cl = kbase + nt * 8 + (lane & 3) * 2 + (e & 1);
                    if (cl > rglo + (e >> 1) * 8) sacc[nt][e] = -1e30f;
                }
        }

        float ml[2] = {-1e30f, -1e30f};
#pragma unroll
        for (int nt = 0; nt < 8; nt++) {
            ml[0] = fmaxf(ml[0], fmaxf(sacc[nt][0], sacc[nt][1]));
            ml[1] = fmaxf(ml[1], fmaxf(sacc[nt][2], sacc[nt][3]));
        }
#pragma unroll
        for (int i = 0; i < 2; i++) {
            ml[i] = fmaxf(ml[i], __shfl_xor_sync(0xffffffffu, ml[i], 1));
            ml[i] = fmaxf(ml[i], __shfl_xor_sync(0xffffffffu, ml[i], 2));
        }
        float mn[2], al[2];
#pragma unroll
        for (int i = 0; i < 2; i++) {
            mn[i] = fmaxf(mrow[i], ml[i]);
            al[i] = exp2f(mrow[i] - mn[i]);
            mrow[i] = mn[i];
        }

        float ls[2] = {0.f, 0.f};
        uint32_t pf[4][4];
#pragma unroll
        for (int nt = 0; nt < 8; nt++) {
            uint32_t p01 = ex2h2(sacc[nt][0] - mn[0], sacc[nt][1] - mn[0]);
            uint32_t p23 = ex2h2(sacc[nt][2] - mn[1], sacc[nt][3] - mn[1]);
            pf[nt >> 1][(nt & 1) * 2 + 0] = p01;
            pf[nt >> 1][(nt & 1) * 2 + 1] = p23;
            float2 f0 = __half22float2(*(__half2*)&p01);
            float2 f1 = __half22float2(*(__half2*)&p23);
            ls[0] += f0.x + f0.y;
            ls[1] += f1.x + f1.y;
        }
#pragma unroll
        for (int i = 0; i < 2; i++) {
            ls[i] += __shfl_xor_sync(0xffffffffu, ls[i], 1);
            ls[i] += __shfl_xor_sync(0xffffffffu, ls[i], 2);
            lrow[i] = lrow[i] * al[i] + ls[i];
        }
#pragma unroll
        for (int nq = 0; nq < 16; nq++) {
            oacc[nq][0] *= al[0]; oacc[nq][1] *= al[0];
            oacc[nq][2] *= al[1]; oacc[nq][3] *= al[1];
        }

#pragma unroll
        for (int kp = 0; kp < 4; kp++) {
            const uint32_t vrow = (uint32_t)(kp * 16 + (lane & 15)) * 272 + lhalf;
#pragma unroll
            for (int np = 0; np < 8; np++) {
                uint32_t vb[4];
                ldm4t(vb, kvst + AVOF + vrow + np * 32);
                mma16816(oacc[2 * np],     pf[kp], vb[0], vb[1]);
                mma16816(oacc[2 * np + 1], pf[kp], vb[2], vb[3]);
            }
        }
    }

#pragma unroll
    for (int i = 0; i < 2; i++) {
        float inv = 1.0f / lrow[i];
        int rl = w * 16 + (lane >> 2) + i * 8;
        __half* Yp = g_yh + (size_t)(b * TQ + qbase + rl) * D_MODEL + h * HD;
#pragma unroll
        for (int nq = 0; nq < 16; nq++) {
            int col = nq * 8 + (lane & 3) * 2;
            *(__half2*)(Yp + col) =
                __floats2half2_rn(oacc[nq][2 * i] * inv, oacc[nq][2 * i + 1] * inv);
        }
    }
}

// =====================================================================
// launch
// =====================================================================
extern "C" void kernel_launch(void* const* d_in, const int* in_sizes, int n_in,
                              void* d_out, int out_size)
{
    const float* x     = (const float*)d_in[0];
    const float* cosb  = (const float*)d_in[1];
    const float* sinb  = (const float*)d_in[2];
    const float* kxl   = (const float*)d_in[3];
    const float* vxl   = (const float*)d_in[4];
    const float* pos   = (const float*)d_in[5];
    const float* wqkv  = (const float*)d_in[6];
    const float* wproj = (const float*)d_in[7];
    const int*   flag  = (const int*)d_in[8];
    float*       out   = (float*)d_out;

    __half *ah, *bh, *bp, *yh;
    cudaGetSymbolAddress((void**)&ah, g_ah);
    cudaGetSymbolAddress((void**)&bh, g_bh);
    cudaGetSymbolAddress((void**)&bp, g_bp);
    cudaGetSymbolAddress((void**)&yh, g_yh);

    cudaFuncSetAttribute(attn_kernel, cudaFuncAttributeMaxDynamicSharedMemorySize, ATTN_SMEM);
    cudaFuncSetAttribute(gemm_mma<0>, cudaFuncAttributeMaxDynamicSharedMemorySize, GEMM_SMEM);
    cudaFuncSetAttribute(gemm_mma<1>, cudaFuncAttributeMaxDynamicSharedMemorySize, GEMM_SMEM);

    // 1) convert x + wqkv (qkv GEMM inputs)
    prep1_kernel<<<4096, 256>>>(x, wqkv);

    // 2) qkv GEMM (fused RoPE + scatter); aux CTAs at y==0 run first
    gemm_mma<1><<<dim3(3 * D_MODEL / 128, MROWS / 128 + 1), 256, GEMM_SMEM>>>(
        ah, bh, nullptr, cosb, sinb, wproj, kxl, vxl, pos,
        MROWS, 3 * D_MODEL, D_MODEL);

    // 3) flash attention -> fp16 y (one wave: 256 CTAs, 2/SM)
    attn_kernel<<<dim3(TQ / 128, BATCH * NHEADS), 256, ATTN_SMEM>>>(flag);

    // 4) out = y @ w_proj^T
    gemm_mma<0><<<dim3(D_MODEL / 128, MROWS / 128), 256, GEMM_SMEM>>>(
        yh, bp, out, nullptr, nullptr, nullptr, nullptr, nullptr, nullptr,
        MROWS, D_MODEL, D_MODEL);
}

// round 16
// speedup vs baseline: 1.5723x; 1.0041x over previous
#include <cuda_runtime.h>
#include <cuda_fp16.h>
#include <cstdint>

#define D_MODEL 2048
#define NHEADS  16
#define HD      128
#define BATCH   2
#define TQ      1024
#define XLLEN   1024
#define KVLEN   2048
#define MROWS   (BATCH * TQ)    // 2048

// ---------------- scratch (device globals) ----------------
__device__ __half g_yh [(size_t)MROWS * D_MODEL];
__device__ __half g_qh [(size_t)BATCH * NHEADS * TQ * HD];
__device__ __half g_kh [(size_t)BATCH * NHEADS * KVLEN * HD];
__device__ __half g_vh [(size_t)BATCH * NHEADS * KVLEN * HD];
__device__ __half g_ah [(size_t)MROWS * D_MODEL];
__device__ __half g_bh [(size_t)3 * D_MODEL * D_MODEL];
__device__ __half g_bp [(size_t)D_MODEL * D_MODEL];
// dependency counters: [0..15]=head_cnt, [16..31]=qt_cnt, [32]=aux_cnt
__device__ int g_cnt[40];

// ======================= PTX helpers =======================
__device__ __forceinline__ uint32_t smem_u32(const void* p) {
    uint32_t a;
    asm("{ .reg .u64 t; cvta.to.shared.u64 t, %1; cvt.u32.u64 %0, t; }" : "=r"(a) : "l"(p));
    return a;
}
__device__ __forceinline__ void ldm4(uint32_t* r, uint32_t a) {
    asm volatile("ldmatrix.sync.aligned.m8n8.x4.shared.b16 {%0,%1,%2,%3}, [%4];"
                 : "=r"(r[0]), "=r"(r[1]), "=r"(r[2]), "=r"(r[3]) : "r"(a));
}
__device__ __forceinline__ void ldm4t(uint32_t* r, uint32_t a) {
    asm volatile("ldmatrix.sync.aligned.m8n8.x4.trans.shared.b16 {%0,%1,%2,%3}, [%4];"
                 : "=r"(r[0]), "=r"(r[1]), "=r"(r[2]), "=r"(r[3]) : "r"(a));
}
__device__ __forceinline__ void mma16816(float* d, const uint32_t* a, uint32_t b0, uint32_t b1) {
    asm volatile("mma.sync.aligned.m16n8k16.row.col.f32.f16.f16.f32 "
                 "{%0,%1,%2,%3}, {%4,%5,%6,%7}, {%8,%9}, {%0,%1,%2,%3};"
                 : "+f"(d[0]), "+f"(d[1]), "+f"(d[2]), "+f"(d[3])
                 : "r"(a[0]), "r"(a[1]), "r"(a[2]), "r"(a[3]), "r"(b0), "r"(b1));
}
__device__ __forceinline__ void cpa16(uint32_t dst, const void* src) {
    asm volatile("cp.async.cg.shared.global [%0], [%1], 16;" :: "r"(dst), "l"(src));
}
__device__ __forceinline__ void cpa_commit() { asm volatile("cp.async.commit_group;" ::: "memory"); }
__device__ __forceinline__ void cpa_wait0()  { asm volatile("cp.async.wait_group 0;" ::: "memory"); }
__device__ __forceinline__ uint32_t ex2h2(float a, float b) {
    __half2 t = __floats2half2_rn(a, b);
    uint32_t u = *(uint32_t*)&t, r;
    asm("ex2.approx.f16x2 %0, %1;" : "=r"(r) : "r"(u));
    return r;
}
__device__ __forceinline__ uint4 cvt8(float4 a, float4 b) {
    __half h[8] = {__float2half_rn(a.x), __float2half_rn(a.y),
                   __float2half_rn(a.z), __float2half_rn(a.w),
                   __float2half_rn(b.x), __float2half_rn(b.y),
                   __float2half_rn(b.z), __float2half_rn(b.w)};
    return *(uint4*)h;
}
__device__ __forceinline__ int gload_acq(const int* p) {
    int v;
    asm volatile("ld.global.acquire.gpu.b32 %0, [%1];" : "=r"(v) : "l"(p));
    return v;
}
// all threads call; signals counter idx
__device__ __forceinline__ void signal_cnt(int idx) {
    __threadfence();
    __syncthreads();
    if (threadIdx.x == 0) atomicAdd(&g_cnt[idx], 1);
}
// tid0 spins until g_cnt[idx] >= tgt (and aux done); then fence + barrier
__device__ __forceinline__ void wait_cnt(int idx, int tgt) {
    if (threadIdx.x == 0) {
        while (gload_acq(&g_cnt[32]) < 48 || gload_acq(&g_cnt[idx]) < tgt)
            __nanosleep(128);
        __threadfence();
    }
    __syncthreads();
}

// =====================================================================
// prep1: zero counters + fp32->fp16 for x + wqkv
// =====================================================================
__global__ void prep1_kernel(const float* __restrict__ x, const float* __restrict__ wqkv)
{
    const int blk = blockIdx.x;       // 4096 blocks
    if (blk == 0 && threadIdx.x < 40) g_cnt[threadIdx.x] = 0;
    const float* src; __half* dst; int i;
    if (blk < 1024) { src = x;    dst = g_ah; i = blk * 256 + threadIdx.x; }
    else            { src = wqkv; dst = g_bh; i = (blk - 1024) * 256 + threadIdx.x; }
    float4 v0 = ((const float4*)src)[4 * i];
    float4 v1 = ((const float4*)src)[4 * i + 1];
    float4 v2 = ((const float4*)src)[4 * i + 2];
    float4 v3 = ((const float4*)src)[4 * i + 3];
    *(uint4*)(dst + (size_t)i * 16)     = cvt8(v0, v1);
    *(uint4*)(dst + (size_t)i * 16 + 8) = cvt8(v2, v3);
}

// =====================================================================
// GEMM body (R15): 128x128 tile, BK=64, 8 warps, 2-stage 176B rows,
// one barrier per 128 mma.  MODE 0: fp32 C.  MODE 1: RoPE+scatter.
// =====================================================================
#define GTILE_B  22528            // 128 rows x 176B
#define GSTG_B   (2 * GTILE_B)    // 45056
#define GEMM_SMEM (2 * GSTG_B)    // 90112
#define MEGA_SMEM 104448          // max(GEMM, ATTN)

template<int MODE>
__device__ void gemm_body(char* smraw,
    const __half* __restrict__ A, const __half* __restrict__ B,
    float* __restrict__ C, const float* __restrict__ cosb, const float* __restrict__ sinb,
    int mb, int nb, int N)
{
    const int K = D_MODEL;
    const uint32_t sb = smem_u32(smraw);
    const int tid = threadIdx.x, wid = tid >> 5, lane = tid & 31;
    const int wm = wid & 1, wn = wid >> 1;

    const __half* Asrc = A + (size_t)mb * K;
    const __half* Bsrc = B + (size_t)nb * K;
    const int NKB = K >> 6;                 // BK = 64
    const int lrow = tid >> 3, lkc = tid & 7;

    {
        const uint32_t st = sb;
#pragma unroll
        for (int i = 0; i < 4; i++) {
            int row = lrow + i * 32;
            cpa16(st + row * 176 + lkc * 16, Asrc + (size_t)row * K + lkc * 8);
            cpa16(st + GTILE_B + row * 176 + lkc * 16, Bsrc + (size_t)row * K + lkc * 8);
        }
        cpa_commit();
    }

    float acc[4][4][4];
#pragma unroll
    for (int a = 0; a < 4; a++)
#pragma unroll
        for (int b = 0; b < 4; b++)
#pragma unroll
            for (int e = 0; e < 4; e++) acc[a][b][e] = 0.f;

    const uint32_t arow = (uint32_t)(wm * 64 + (lane & 15)) * 176;
    const uint32_t brow = (uint32_t)(wn * 32 + (lane & 15)) * 176;
    const uint32_t lhalf = (lane >> 4) * 16;

    for (int kb = 0; kb < NKB; kb++) {
        cpa_wait0();
        __syncthreads();
        const uint32_t st = sb + (kb & 1) * GSTG_B;

        if (kb + 1 < NKB) {
            const uint32_t pst = sb + ((kb + 1) & 1) * GSTG_B;
            const int ko = (kb + 1) * 64;
#pragma unroll
            for (int i = 0; i < 4; i++) {
                int row = lrow + i * 32;
                cpa16(pst + row * 176 + lkc * 16, Asrc + (size_t)row * K + ko + lkc * 8);
                cpa16(pst + GTILE_B + row * 176 + lkc * 16, Bsrc + (size_t)row * K + ko + lkc * 8);
            }
            cpa_commit();
        }

#pragma unroll
        for (int ks = 0; ks < 4; ks++) {
            const uint32_t koff = ks * 32 + lhalf;
            uint32_t Af[4][4], Bf[2][4];
#pragma unroll
            for (int mt = 0; mt < 4; mt++)
                ldm4(Af[mt], st + arow + mt * 16 * 176 + koff);
#pragma unroll
            for (int np = 0; np < 2; np++)
                ldm4(Bf[np], st + GTILE_B + brow + np * 16 * 176 + koff);
#pragma unroll
            for (int mt = 0; mt < 4; mt++)
#pragma unroll
                for (int nt = 0; nt < 4; nt++)
                    mma16816(acc[mt][nt], Af[mt], Bf[nt >> 1][nt & 1], Bf[nt >> 1][(nt & 1) + 2]);
        }
    }

    if (MODE == 0) {
#pragma unroll
        for (int mt = 0; mt < 4; mt++) {
            int row0 = mb + wm * 64 + mt * 16 + (lane >> 2);
#pragma unroll
            for (int nt = 0; nt < 4; nt++) {
                int col = nb + wn * 32 + nt * 8 + (lane & 3) * 2;
                *(float2*)&C[(size_t)row0 * N + col]       = make_float2(acc[mt][nt][0], acc[mt][nt][1]);
                *(float2*)&C[(size_t)(row0 + 8) * N + col] = make_float2(acc[mt][nt][2], acc[mt][nt][3]);
            }
        }
    } else {
        const int region = nb >> 11;
        const int hh = (nb & 2047) >> 7;
#pragma unroll
        for (int mt = 0; mt < 4; mt++) {
#pragma unroll
            for (int i = 0; i < 2; i++) {
                int row = mb + wm * 64 + mt * 16 + (lane >> 2) + i * 8;
                int bb = row >> 10, t = row & 1023;
#pragma unroll
                for (int nt = 0; nt < 4; nt++) {
                    int d = wn * 32 + nt * 8 + (lane & 3) * 2;
                    float a0 = acc[mt][nt][2 * i], a1 = acc[mt][nt][2 * i + 1];
                    if (region == 2) {
                        size_t dst = ((size_t)(bb * NHEADS + hh) * KVLEN + XLLEN + t) * HD + d;
                        *(__half2*)&g_vh[dst] = __floats2half2_rn(a0, a1);
                    } else {
                        int dp = d >> 1;
                        float cv = cosb[t * 64 + dp], sv = sinb[t * 64 + dp];
                        float o0 = a0 * cv - a1 * sv;
                        float o1 = a0 * sv + a1 * cv;
                        if (region == 0) {
                            size_t dst = ((size_t)(bb * NHEADS + hh) * TQ + t) * HD + d;
                            *(__half2*)&g_qh[dst] = __floats2half2_rn(o0, o1);
                        } else {
                            size_t dst = ((size_t)(bb * NHEADS + hh) * KVLEN + XLLEN + t) * HD + d;
                            *(__half2*)&g_kh[dst] = __floats2half2_rn(o0, o1);
                        }
                    }
                }
            }
        }
    }
}

// =====================================================================
// attention body (R14/R15): BQ=128, BK=64, 8 warps, 2-stage KV
// =====================================================================
#define AQSZ   34816
#define AKV    AQSZ
#define AKVSTG 34816
#define AVOF   17408

__device__ void attn_body(char* smraw, int qt, int bh, int causal)
{
    const uint32_t sb = smem_u32(smraw);
    const int tid = threadIdx.x, w = tid >> 5, lane = tid & 31;
    const int b = bh >> 4, h = bh & 15;
    const int qbase = qt * 128;

    const __half* Qh = g_qh + (size_t)bh * (TQ * HD);
    const __half* Kh = g_kh + (size_t)bh * (KVLEN * HD);
    const __half* Vh = g_vh + (size_t)bh * (KVLEN * HD);

    int ntile = causal ? (2 * qt + 18) : 32;
    if (ntile > 32) ntile = 32;

#pragma unroll
    for (int i = 0; i < 8; i++) {
        int c = tid + i * 256;
        int row = c >> 4, kc = c & 15;
        cpa16(sb + row * 272 + kc * 16, Qh + (size_t)(qbase + row) * HD + kc * 8);
    }
    cpa_commit();
#pragma unroll
    for (int i = 0; i < 4; i++) {
        int c = tid + i * 256;
        int row = c >> 4, kc = c & 15;
        cpa16(sb + AKV + row * 272 + kc * 16, Kh + (size_t)row * HD + kc * 8);
        cpa16(sb + AKV + AVOF + row * 272 + kc * 16, Vh + (size_t)row * HD + kc * 8);
    }
    cpa_commit();

    float oacc[16][4];
#pragma unroll
    for (int nq = 0; nq < 16; nq++)
#pragma unroll
        for (int e = 0; e < 4; e++) oacc[nq][e] = 0.f;
    float mrow[2] = {-1e30f, -1e30f}, lrow[2] = {0.f, 0.f};

    const float scale2 = 0.12751879523525493f;
    const int roff = KVLEN - TQ;
    const uint32_t qrow = (uint32_t)(w * 16 + (lane & 15)) * 272;
    const uint32_t krow = (uint32_t)(lane & 15) * 272;
    const uint32_t lhalf = (lane >> 4) * 16;

    for (int kt = 0; kt < ntile; kt++) {
        cpa_wait0();
        __syncthreads();
        const uint32_t kvst = sb + AKV + (kt & 1) * AKVSTG;

        if (kt + 1 < ntile) {
            const uint32_t st = sb + AKV + ((kt + 1) & 1) * AKVSTG;
            const int kb0 = (kt + 1) * 64;
#pragma unroll
            for (int i = 0; i < 4; i++) {
                int c = tid + i * 256;
                int row = c >> 4, kc = c & 15;
                cpa16(st + row * 272 + kc * 16, Kh + (size_t)(kb0 + row) * HD + kc * 8);
                cpa16(st + AVOF + row * 272 + kc * 16, Vh + (size_t)(kb0 + row) * HD + kc * 8);
            }
            cpa_commit();
        }

        float sacc[8][4];
#pragma unroll
        for (int nt = 0; nt < 8; nt++)
#pragma unroll
            for (int e = 0; e < 4; e++) sacc[nt][e] = 0.f;

#pragma unroll
        for (int ks = 0; ks < 8; ks++) {
            const uint32_t koff = ks * 32 + lhalf;
            uint32_t qf[4];
            ldm4(qf, sb + qrow + koff);
#pragma unroll
            for (int np = 0; np < 4; np++) {
                uint32_t kf[4];
                ldm4(kf, kvst + krow + np * 16 * 272 + koff);
                mma16816(sacc[2 * np],     qf, kf[0], kf[2]);
                mma16816(sacc[2 * np + 1], qf, kf[1], kf[3]);
            }
        }

#pragma unroll
        for (int nt = 0; nt < 8; nt++)
#pragma unroll
            for (int e = 0; e < 4; e++) sacc[nt][e] *= scale2;
        if (causal) {
            const int kbase = kt * 64;
            const int rglo = qbase + w * 16 + (lane >> 2) + roff;
#pragma unroll
            for (int nt = 0; nt < 8; nt++)
#pragma unroll
                for (int e = 0; e < 4; e++) {
                    int cl = kbase + nt * 8 + (lane & 3) * 2 + (e & 1);
                    if (cl > rglo + (e >> 1) * 8) sacc[nt][e] = -1e30f;
                }
        }

        float ml[2] = {-1e30f, -1e30f};
#pragma unroll
        for (int nt = 0; nt < 8; nt++) {
            ml[0] = fmaxf(ml[0], fmaxf(sacc[nt][0], sacc[nt][1]));
            ml[1] = fmaxf(ml[1], fmaxf(sacc[nt][2], sacc[nt][3]));
        }
#pragma unroll
        for (int i = 0; i < 2; i++) {
            ml[i] = fmaxf(ml[i], __shfl_xor_sync(0xffffffffu, ml[i], 1));
            ml[i] = fmaxf(ml[i], __shfl_xor_sync(0xffffffffu, ml[i], 2));
        }
        float mn[2], al[2];
#pragma unroll
        for (int i = 0; i < 2; i++) {
            mn[i] = fmaxf(mrow[i], ml[i]);
            al[i] = exp2f(mrow[i] - mn[i]);
            mrow[i] = mn[i];
        }

        float ls[2] = {0.f, 0.f};
        uint32_t pf[4][4];
#pragma unroll
        for (int nt = 0; nt < 8; nt++) {
            uint32_t p01 = ex2h2(sacc[nt][0] - mn[0], sacc[nt][1] - mn[0]);
            uint32_t p23 = ex2h2(sacc[nt][2] - mn[1], sacc[nt][3] - mn[1]);
            pf[nt >> 1][(nt & 1) * 2 + 0] = p01;
            pf[nt >> 1][(nt & 1) * 2 + 1] = p23;
            float2 f0 = __half22float2(*(__half2*)&p01);
            float2 f1 = __half22float2(*(__half2*)&p23);
            ls[0] += f0.x + f0.y;
            ls[1] += f1.x + f1.y;
        }
#pragma unroll
        for (int i = 0; i < 2; i++) {
            ls[i] += __shfl_xor_sync(0xffffffffu, ls[i], 1);
            ls[i] += __shfl_xor_sync(0xffffffffu, ls[i], 2);
            lrow[i] = lrow[i] * al[i] + ls[i];
        }
#pragma unroll
        for (int nq = 0; nq < 16; nq++) {
            oacc[nq][0] *= al[0]; oacc[nq][1] *= al[0];
            oacc[nq][2] *= al[1]; oacc[nq][3] *= al[1];
        }

#pragma unroll
        for (int kp = 0; kp < 4; kp++) {
            const uint32_t vrow = (uint32_t)(kp * 16 + (lane & 15)) * 272 + lhalf;
#pragma unroll
            for (int np = 0; np < 8; np++) {
                uint32_t vb[4];
                ldm4t(vb, kvst + AVOF + vrow + np * 32);
                mma16816(oacc[2 * np],     pf[kp], vb[0], vb[1]);
                mma16816(oacc[2 * np + 1], pf[kp], vb[2], vb[3]);
            }
        }
    }

#pragma unroll
    for (int i = 0; i < 2; i++) {
        float inv = 1.0f / lrow[i];
        int rl = w * 16 + (lane >> 2) + i * 8;
        __half* Yp = g_yh + (size_t)(b * TQ + qbase + rl) * D_MODEL + h * HD;
#pragma unroll
        for (int nq = 0; nq < 16; nq++) {
            int col = nq * 8 + (lane & 3) * 2;
            *(__half2*)(Yp + col) =
                __floats2half2_rn(oacc[nq][2 * i] * inv, oacc[nq][2 * i + 1] * inv);
        }
    }
}

// =====================================================================
// megakernel: [0,48) aux | [48,816) qkv col-major | [816,1072) attn |
// [1072,1328) proj — consumers spin on producer counters.
// =====================================================================
#define AUX_NW   (D_MODEL * D_MODEL / 8)
#define AUX_NX   (BATCH * XLLEN * D_MODEL / 8)
#define AUX_THREADS (48 * 256)

__global__ __launch_bounds__(256, 2) void mega_kernel(
    const __half* __restrict__ ah, const __half* __restrict__ bh,
    const float* __restrict__ cosb, const float* __restrict__ sinb,
    const float* __restrict__ wproj, const float* __restrict__ kxl,
    const float* __restrict__ vxl, const float* __restrict__ pos,
    const int* __restrict__ flag, float* __restrict__ out)
{
    extern __shared__ __align__(16) char smraw[];
    const int bid = blockIdx.x;

    if (bid < 48) {
        // ---- aux: wproj conversion + XL K/V prep ----
        int tg = bid * 256 + threadIdx.x;
        for (int u = tg; u < AUX_NW + AUX_NX; u += AUX_THREADS) {
            if (u < AUX_NW) {
                float4 v0 = ((const float4*)wproj)[2 * u];
                float4 v1 = ((const float4*)wproj)[2 * u + 1];
                *(uint4*)(g_bp + (size_t)u * 8) = cvt8(v0, v1);
            } else {
                int idx = u - AUX_NW;
                int d8 = idx & 15;
                int h  = (idx >> 4) & 15;
                int t  = (idx >> 8) & 1023;
                int b  = idx >> 18;
                size_t src = ((size_t)(b * XLLEN + t)) * D_MODEL + h * HD + d8 * 8;
                size_t ps  = (size_t)t * D_MODEL + h * HD + d8 * 8;
                float4 k0 = *(const float4*)(kxl + src), k1 = *(const float4*)(kxl + src + 4);
                float4 p0 = *(const float4*)(pos + ps),  p1 = *(const float4*)(pos + ps + 4);
                float4 v0 = *(const float4*)(vxl + src), v1 = *(const float4*)(vxl + src + 4);
                k0.x += p0.x; k0.y += p0.y; k0.z += p0.z; k0.w += p0.w;
                k1.x += p1.x; k1.y += p1.y; k1.z += p1.z; k1.w += p1.w;
                size_t dst = ((size_t)((b * NHEADS + h) * KVLEN + t)) * HD + d8 * 8;
                *(uint4*)&g_kh[dst] = cvt8(k0, k1);
                *(uint4*)&g_vh[dst] = cvt8(v0, v1);
            }
        }
        signal_cnt(32);
    } else if (bid < 816) {
        // ---- qkv GEMM, column-major order ----
        int q = bid - 48;
        int col = q >> 4, row = q & 15;
        gemm_body<1>(smraw, ah, bh, nullptr, cosb, sinb,
                     row * 128, col * 128, 3 * D_MODEL);
        signal_cnt(col & 15);
    } else if (bid < 1072) {
        // ---- attention, h-major order ----
        int a = bid - 816;
        int h = a >> 4, rest = a & 15;
        int b = rest >> 3, qt = rest & 7;
        wait_cnt(h, 48);
        attn_body(smraw, qt, b * 16 + h, *flag);
        signal_cnt(16 + b * 8 + qt);
    } else {
        // ---- proj GEMM ----
        int p = bid - 1072;
        int m = p >> 4, nc = p & 15;
        wait_cnt(16 + m, 16);
        gemm_body<0>(smraw, g_yh, g_bp, out, nullptr, nullptr,
                     m * 128, nc * 128, D_MODEL);
    }
}

// =====================================================================
// launch
// =====================================================================
extern "C" void kernel_launch(void* const* d_in, const int* in_sizes, int n_in,
                              void* d_out, int out_size)
{
    const float* x     = (const float*)d_in[0];
    const float* cosb  = (const float*)d_in[1];
    const float* sinb  = (const float*)d_in[2];
    const float* kxl   = (const float*)d_in[3];
    const float* vxl   = (const float*)d_in[4];
    const float* pos   = (const float*)d_in[5];
    const float* wqkv  = (const float*)d_in[6];
    const float* wproj = (const float*)d_in[7];
    const int*   flag  = (const int*)d_in[8];
    float*       out   = (float*)d_out;

    __half *ah, *bh;
    cudaGetSymbolAddress((void**)&ah, g_ah);
    cudaGetSymbolAddress((void**)&bh, g_bh);

    cudaFuncSetAttribute(mega_kernel, cudaFuncAttributeMaxDynamicSharedMemorySize, MEGA_SMEM);

    // 1) zero counters + convert x + wqkv
    prep1_kernel<<<4096, 256>>>(x, wqkv);

    // 2) everything else: aux + qkv + attn + proj with in-kernel deps
    mega_kernel<<<1328, 256, MEGA_SMEM>>>(ah, bh, cosb, sinb, wproj,
                                          kxl, vxl, pos, flag, out);
}

// round 17
// speedup vs baseline: 1.5820x; 1.0061x over previous
#include <cuda_runtime.h>
#include <cuda_fp16.h>
#include <cstdint>

#define D_MODEL 2048
#define NHEADS  16
#define HD      128
#define BATCH   2
#define TQ      1024
#define XLLEN   1024
#define KVLEN   2048
#define MROWS   (BATCH * TQ)    // 2048

// ---------------- scratch (device globals) ----------------
__device__ __half g_yh [(size_t)MROWS * D_MODEL];
__device__ __half g_qh [(size_t)BATCH * NHEADS * TQ * HD];
__device__ __half g_kh [(size_t)BATCH * NHEADS * KVLEN * HD];
__device__ __half g_vh [(size_t)BATCH * NHEADS * KVLEN * HD];
__device__ __half g_ah [(size_t)MROWS * D_MODEL];
__device__ __half g_bh [(size_t)3 * D_MODEL * D_MODEL];
__device__ __half g_bp [(size_t)D_MODEL * D_MODEL];
// dependency counters: [0..15]=head_cnt, [16..31]=qt_cnt, [32]=aux_cnt
__device__ int g_cnt[40];

// ======================= PTX helpers =======================
__device__ __forceinline__ uint32_t smem_u32(const void* p) {
    uint32_t a;
    asm("{ .reg .u64 t; cvta.to.shared.u64 t, %1; cvt.u32.u64 %0, t; }" : "=r"(a) : "l"(p));
    return a;
}
__device__ __forceinline__ void ldm4(uint32_t* r, uint32_t a) {
    asm volatile("ldmatrix.sync.aligned.m8n8.x4.shared.b16 {%0,%1,%2,%3}, [%4];"
                 : "=r"(r[0]), "=r"(r[1]), "=r"(r[2]), "=r"(r[3]) : "r"(a));
}
__device__ __forceinline__ void ldm4t(uint32_t* r, uint32_t a) {
    asm volatile("ldmatrix.sync.aligned.m8n8.x4.trans.shared.b16 {%0,%1,%2,%3}, [%4];"
                 : "=r"(r[0]), "=r"(r[1]), "=r"(r[2]), "=r"(r[3]) : "r"(a));
}
__device__ __forceinline__ void mma16816(float* d, const uint32_t* a, uint32_t b0, uint32_t b1) {
    asm volatile("mma.sync.aligned.m16n8k16.row.col.f32.f16.f16.f32 "
                 "{%0,%1,%2,%3}, {%4,%5,%6,%7}, {%8,%9}, {%0,%1,%2,%3};"
                 : "+f"(d[0]), "+f"(d[1]), "+f"(d[2]), "+f"(d[3])
                 : "r"(a[0]), "r"(a[1]), "r"(a[2]), "r"(a[3]), "r"(b0), "r"(b1));
}
__device__ __forceinline__ void cpa16(uint32_t dst, const void* src) {
    asm volatile("cp.async.cg.shared.global [%0], [%1], 16;" :: "r"(dst), "l"(src));
}
__device__ __forceinline__ void cpa_commit() { asm volatile("cp.async.commit_group;" ::: "memory"); }
__device__ __forceinline__ void cpa_wait0()  { asm volatile("cp.async.wait_group 0;" ::: "memory"); }
__device__ __forceinline__ uint32_t ex2h2(float a, float b) {
    __half2 t = __floats2half2_rn(a, b);
    uint32_t u = *(uint32_t*)&t, r;
    asm("ex2.approx.f16x2 %0, %1;" : "=r"(r) : "r"(u));
    return r;
}
__device__ __forceinline__ uint4 cvt8(float4 a, float4 b) {
    __half h[8] = {__float2half_rn(a.x), __float2half_rn(a.y),
                   __float2half_rn(a.z), __float2half_rn(a.w),
                   __float2half_rn(b.x), __float2half_rn(b.y),
                   __float2half_rn(b.z), __float2half_rn(b.w)};
    return *(uint4*)h;
}
__device__ __forceinline__ int gload_acq(const int* p) {
    int v;
    asm volatile("ld.global.acquire.gpu.b32 %0, [%1];" : "=r"(v) : "l"(p));
    return v;
}
__device__ __forceinline__ void signal_cnt(int idx) {
    __threadfence();
    __syncthreads();
    if (threadIdx.x == 0) atomicAdd(&g_cnt[idx], 1);
}
__device__ __forceinline__ void wait_cnt(int idx, int tgt) {
    if (threadIdx.x == 0) {
        while (gload_acq(&g_cnt[32]) < 48 || gload_acq(&g_cnt[idx]) < tgt)
            __nanosleep(128);
        __threadfence();
    }
    __syncthreads();
}

// =====================================================================
// prep1: zero counters + fp32->fp16 for x + wqkv
// =====================================================================
__global__ void prep1_kernel(const float* __restrict__ x, const float* __restrict__ wqkv)
{
    const int blk = blockIdx.x;       // 4096 blocks
    if (blk == 0 && threadIdx.x < 40) g_cnt[threadIdx.x] = 0;
    const float* src; __half* dst; int i;
    if (blk < 1024) { src = x;    dst = g_ah; i = blk * 256 + threadIdx.x; }
    else            { src = wqkv; dst = g_bh; i = (blk - 1024) * 256 + threadIdx.x; }
    float4 v0 = ((const float4*)src)[4 * i];
    float4 v1 = ((const float4*)src)[4 * i + 1];
    float4 v2 = ((const float4*)src)[4 * i + 2];
    float4 v3 = ((const float4*)src)[4 * i + 3];
    *(uint4*)(dst + (size_t)i * 16)     = cvt8(v0, v1);
    *(uint4*)(dst + (size_t)i * 16 + 8) = cvt8(v2, v3);
}

// =====================================================================
// GEMM body (R15): 128x128 tile, BK=64, 8 warps, 2-stage 176B rows,
// one barrier per 128 mma.  MODE 0: fp32 C.  MODE 1: RoPE+scatter.
// =====================================================================
#define GTILE_B  22528            // 128 rows x 176B
#define GSTG_B   (2 * GTILE_B)    // 45056
#define GEMM_SMEM (2 * GSTG_B)    // 90112
#define MEGA_SMEM 104448          // max(GEMM, ATTN)

template<int MODE>
__device__ void gemm_body(char* smraw,
    const __half* __restrict__ A, const __half* __restrict__ B,
    float* __restrict__ C, const float* __restrict__ cosb, const float* __restrict__ sinb,
    int mb, int nb, int N)
{
    const int K = D_MODEL;
    const uint32_t sb = smem_u32(smraw);
    const int tid = threadIdx.x, wid = tid >> 5, lane = tid & 31;
    const int wm = wid & 1, wn = wid >> 1;

    const __half* Asrc = A + (size_t)mb * K;
    const __half* Bsrc = B + (size_t)nb * K;
    const int NKB = K >> 6;                 // BK = 64
    const int lrow = tid >> 3, lkc = tid & 7;

    {
        const uint32_t st = sb;
#pragma unroll
        for (int i = 0; i < 4; i++) {
            int row = lrow + i * 32;
            cpa16(st + row * 176 + lkc * 16, Asrc + (size_t)row * K + lkc * 8);
            cpa16(st + GTILE_B + row * 176 + lkc * 16, Bsrc + (size_t)row * K + lkc * 8);
        }
        cpa_commit();
    }

    float acc[4][4][4];
#pragma unroll
    for (int a = 0; a < 4; a++)
#pragma unroll
        for (int b = 0; b < 4; b++)
#pragma unroll
            for (int e = 0; e < 4; e++) acc[a][b][e] = 0.f;

    const uint32_t arow = (uint32_t)(wm * 64 + (lane & 15)) * 176;
    const uint32_t brow = (uint32_t)(wn * 32 + (lane & 15)) * 176;
    const uint32_t lhalf = (lane >> 4) * 16;

    for (int kb = 0; kb < NKB; kb++) {
        cpa_wait0();
        __syncthreads();
        const uint32_t st = sb + (kb & 1) * GSTG_B;

        if (kb + 1 < NKB) {
            const uint32_t pst = sb + ((kb + 1) & 1) * GSTG_B;
            const int ko = (kb + 1) * 64;
#pragma unroll
            for (int i = 0; i < 4; i++) {
                int row = lrow + i * 32;
                cpa16(pst + row * 176 + lkc * 16, Asrc + (size_t)row * K + ko + lkc * 8);
                cpa16(pst + GTILE_B + row * 176 + lkc * 16, Bsrc + (size_t)row * K + ko + lkc * 8);
            }
            cpa_commit();
        }

#pragma unroll
        for (int ks = 0; ks < 4; ks++) {
            const uint32_t koff = ks * 32 + lhalf;
            uint32_t Af[4][4], Bf[2][4];
#pragma unroll
            for (int mt = 0; mt < 4; mt++)
                ldm4(Af[mt], st + arow + mt * 16 * 176 + koff);
#pragma unroll
            for (int np = 0; np < 2; np++)
                ldm4(Bf[np], st + GTILE_B + brow + np * 16 * 176 + koff);
#pragma unroll
            for (int mt = 0; mt < 4; mt++)
#pragma unroll
                for (int nt = 0; nt < 4; nt++)
                    mma16816(acc[mt][nt], Af[mt], Bf[nt >> 1][nt & 1], Bf[nt >> 1][(nt & 1) + 2]);
        }
    }

    if (MODE == 0) {
#pragma unroll
        for (int mt = 0; mt < 4; mt++) {
            int row0 = mb + wm * 64 + mt * 16 + (lane >> 2);
#pragma unroll
            for (int nt = 0; nt < 4; nt++) {
                int col = nb + wn * 32 + nt * 8 + (lane & 3) * 2;
                *(float2*)&C[(size_t)row0 * N + col]       = make_float2(acc[mt][nt][0], acc[mt][nt][1]);
                *(float2*)&C[(size_t)(row0 + 8) * N + col] = make_float2(acc[mt][nt][2], acc[mt][nt][3]);
            }
        }
    } else {
        const int region = nb >> 11;
        const int hh = (nb & 2047) >> 7;
#pragma unroll
        for (int mt = 0; mt < 4; mt++) {
#pragma unroll
            for (int i = 0; i < 2; i++) {
                int row = mb + wm * 64 + mt * 16 + (lane >> 2) + i * 8;
                int bb = row >> 10, t = row & 1023;
#pragma unroll
                for (int nt = 0; nt < 4; nt++) {
                    int d = wn * 32 + nt * 8 + (lane & 3) * 2;
                    float a0 = acc[mt][nt][2 * i], a1 = acc[mt][nt][2 * i + 1];
                    if (region == 2) {
                        size_t dst = ((size_t)(bb * NHEADS + hh) * KVLEN + XLLEN + t) * HD + d;
                        *(__half2*)&g_vh[dst] = __floats2half2_rn(a0, a1);
                    } else {
                        int dp = d >> 1;
                        float cv = cosb[t * 64 + dp], sv = sinb[t * 64 + dp];
                        float o0 = a0 * cv - a1 * sv;
                        float o1 = a0 * sv + a1 * cv;
                        if (region == 0) {
                            size_t dst = ((size_t)(bb * NHEADS + hh) * TQ + t) * HD + d;
                            *(__half2*)&g_qh[dst] = __floats2half2_rn(o0, o1);
                        } else {
                            size_t dst = ((size_t)(bb * NHEADS + hh) * KVLEN + XLLEN + t) * HD + d;
                            *(__half2*)&g_kh[dst] = __floats2half2_rn(o0, o1);
                        }
                    }
                }
            }
        }
    }
}

// =====================================================================
// attention body (R14/R15): BQ=128, BK=64, 8 warps, 2-stage KV
// =====================================================================
#define AQSZ   34816
#define AKV    AQSZ
#define AKVSTG 34816
#define AVOF   17408

__device__ void attn_body(char* smraw, int qt, int bh, int causal)
{
    const uint32_t sb = smem_u32(smraw);
    const int tid = threadIdx.x, w = tid >> 5, lane = tid & 31;
    const int b = bh >> 4, h = bh & 15;
    const int qbase = qt * 128;

    const __half* Qh = g_qh + (size_t)bh * (TQ * HD);
    const __half* Kh = g_kh + (size_t)bh * (KVLEN * HD);
    const __half* Vh = g_vh + (size_t)bh * (KVLEN * HD);

    int ntile = causal ? (2 * qt + 18) : 32;
    if (ntile > 32) ntile = 32;

#pragma unroll
    for (int i = 0; i < 8; i++) {
        int c = tid + i * 256;
        int row = c >> 4, kc = c & 15;
        cpa16(sb + row * 272 + kc * 16, Qh + (size_t)(qbase + row) * HD + kc * 8);
    }
    cpa_commit();
#pragma unroll
    for (int i = 0; i < 4; i++) {
        int c = tid + i * 256;
        int row = c >> 4, kc = c & 15;
        cpa16(sb + AKV + row * 272 + kc * 16, Kh + (size_t)row * HD + kc * 8);
        cpa16(sb + AKV + AVOF + row * 272 + kc * 16, Vh + (size_t)row * HD + kc * 8);
    }
    cpa_commit();

    float oacc[16][4];
#pragma unroll
    for (int nq = 0; nq < 16; nq++)
#pragma unroll
        for (int e = 0; e < 4; e++) oacc[nq][e] = 0.f;
    float mrow[2] = {-1e30f, -1e30f}, lrow[2] = {0.f, 0.f};

    const float scale2 = 0.12751879523525493f;
    const int roff = KVLEN - TQ;
    const uint32_t qrow = (uint32_t)(w * 16 + (lane & 15)) * 272;
    const uint32_t krow = (uint32_t)(lane & 15) * 272;
    const uint32_t lhalf = (lane >> 4) * 16;

    for (int kt = 0; kt < ntile; kt++) {
        cpa_wait0();
        __syncthreads();
        const uint32_t kvst = sb + AKV + (kt & 1) * AKVSTG;

        if (kt + 1 < ntile) {
            const uint32_t st = sb + AKV + ((kt + 1) & 1) * AKVSTG;
            const int kb0 = (kt + 1) * 64;
#pragma unroll
            for (int i = 0; i < 4; i++) {
                int c = tid + i * 256;
                int row = c >> 4, kc = c & 15;
                cpa16(st + row * 272 + kc * 16, Kh + (size_t)(kb0 + row) * HD + kc * 8);
                cpa16(st + AVOF + row * 272 + kc * 16, Vh + (size_t)(kb0 + row) * HD + kc * 8);
            }
            cpa_commit();
        }

        float sacc[8][4];
#pragma unroll
        for (int nt = 0; nt < 8; nt++)
#pragma unroll
            for (int e = 0; e < 4; e++) sacc[nt][e] = 0.f;

#pragma unroll
        for (int ks = 0; ks < 8; ks++) {
            const uint32_t koff = ks * 32 + lhalf;
            uint32_t qf[4];
            ldm4(qf, sb + qrow + koff);
#pragma unroll
            for (int np = 0; np < 4; np++) {
                uint32_t kf[4];
                ldm4(kf, kvst + krow + np * 16 * 272 + koff);
                mma16816(sacc[2 * np],     qf, kf[0], kf[2]);
                mma16816(sacc[2 * np + 1], qf, kf[1], kf[3]);
            }
        }

#pragma unroll
        for (int nt = 0; nt < 8; nt++)
#pragma unroll
            for (int e = 0; e < 4; e++) sacc[nt][e] *= scale2;
        if (causal) {
            const int kbase = kt * 64;
            const int rglo = qbase + w * 16 + (lane >> 2) + roff;
#pragma unroll
            for (int nt = 0; nt < 8; nt++)
#pragma unroll
                for (int e = 0; e < 4; e++) {
                    int cl = kbase + nt * 8 + (lane & 3) * 2 + (e & 1);
                    if (cl > rglo + (e >> 1) * 8) sacc[nt][e] = -1e30f;
                }
        }

        float ml[2] = {-1e30f, -1e30f};
#pragma unroll
        for (int nt = 0; nt < 8; nt++) {
            ml[0] = fmaxf(ml[0], fmaxf(sacc[nt][0], sacc[nt][1]));
            ml[1] = fmaxf(ml[1], fmaxf(sacc[nt][2], sacc[nt][3]));
        }
#pragma unroll
        for (int i = 0; i < 2; i++) {
            ml[i] = fmaxf(ml[i], __shfl_xor_sync(0xffffffffu, ml[i], 1));
            ml[i] = fmaxf(ml[i], __shfl_xor_sync(0xffffffffu, ml[i], 2));
        }
        float mn[2], al[2];
#pragma unroll
        for (int i = 0; i < 2; i++) {
            mn[i] = fmaxf(mrow[i], ml[i]);
            al[i] = exp2f(mrow[i] - mn[i]);
            mrow[i] = mn[i];
        }

        float ls[2] = {0.f, 0.f};
        uint32_t pf[4][4];
#pragma unroll
        for (int nt = 0; nt < 8; nt++) {
            uint32_t p01 = ex2h2(sacc[nt][0] - mn[0], sacc[nt][1] - mn[0]);
            uint32_t p23 = ex2h2(sacc[nt][2] - mn[1], sacc[nt][3] - mn[1]);
            pf[nt >> 1][(nt & 1) * 2 + 0] = p01;
            pf[nt >> 1][(nt & 1) * 2 + 1] = p23;
            float2 f0 = __half22float2(*(__half2*)&p01);
            float2 f1 = __half22float2(*(__half2*)&p23);
            ls[0] += f0.x + f0.y;
            ls[1] += f1.x + f1.y;
        }
#pragma unroll
        for (int i = 0; i < 2; i++) {
            ls[i] += __shfl_xor_sync(0xffffffffu, ls[i], 1);
            ls[i] += __shfl_xor_sync(0xffffffffu, ls[i], 2);
            lrow[i] = lrow[i] * al[i] + ls[i];
        }
#pragma unroll
        for (int nq = 0; nq < 16; nq++) {
            oacc[nq][0] *= al[0]; oacc[nq][1] *= al[0];
            oacc[nq][2] *= al[1]; oacc[nq][3] *= al[1];
        }

#pragma unroll
        for (int kp = 0; kp < 4; kp++) {
            const uint32_t vrow = (uint32_t)(kp * 16 + (lane & 15)) * 272 + lhalf;
#pragma unroll
            for (int np = 0; np < 8; np++) {
                uint32_t vb[4];
                ldm4t(vb, kvst + AVOF + vrow + np * 32);
                mma16816(oacc[2 * np],     pf[kp], vb[0], vb[1]);
                mma16816(oacc[2 * np + 1], pf[kp], vb[2], vb[3]);
            }
        }
    }

#pragma unroll
    for (int i = 0; i < 2; i++) {
        float inv = 1.0f / lrow[i];
        int rl = w * 16 + (lane >> 2) + i * 8;
        __half* Yp = g_yh + (size_t)(b * TQ + qbase + rl) * D_MODEL + h * HD;
#pragma unroll
        for (int nq = 0; nq < 16; nq++) {
            int col = nq * 8 + (lane & 3) * 2;
            *(__half2*)(Yp + col) =
                __floats2half2_rn(oacc[nq][2 * i] * inv, oacc[nq][2 * i + 1] * inv);
        }
    }
}

// =====================================================================
// megakernel: [0,48) aux | [48,816) qkv HEAD-MAJOR cols | [816,1072)
// attn h-major | [1072,1328) proj — consumers spin on counters.
// =====================================================================
#define AUX_NW   (D_MODEL * D_MODEL / 8)
#define AUX_NX   (BATCH * XLLEN * D_MODEL / 8)
#define AUX_THREADS (48 * 256)

__global__ __launch_bounds__(256, 2) void mega_kernel(
    const __half* __restrict__ ah, const __half* __restrict__ bh,
    const float* __restrict__ cosb, const float* __restrict__ sinb,
    const float* __restrict__ wproj, const float* __restrict__ kxl,
    const float* __restrict__ vxl, const float* __restrict__ pos,
    const int* __restrict__ flag, float* __restrict__ out)
{
    extern __shared__ __align__(16) char smraw[];
    const int bid = blockIdx.x;

    if (bid < 48) {
        // ---- aux: wproj conversion + XL K/V prep ----
        int tg = bid * 256 + threadIdx.x;
        for (int u = tg; u < AUX_NW + AUX_NX; u += AUX_THREADS) {
            if (u < AUX_NW) {
                float4 v0 = ((const float4*)wproj)[2 * u];
                float4 v1 = ((const float4*)wproj)[2 * u + 1];
                *(uint4*)(g_bp + (size_t)u * 8) = cvt8(v0, v1);
            } else {
                int idx = u - AUX_NW;
                int d8 = idx & 15;
                int h  = (idx >> 4) & 15;
                int t  = (idx >> 8) & 1023;
                int b  = idx >> 18;
                size_t src = ((size_t)(b * XLLEN + t)) * D_MODEL + h * HD + d8 * 8;
                size_t ps  = (size_t)t * D_MODEL + h * HD + d8 * 8;
                float4 k0 = *(const float4*)(kxl + src), k1 = *(const float4*)(kxl + src + 4);
                float4 p0 = *(const float4*)(pos + ps),  p1 = *(const float4*)(pos + ps + 4);
                float4 v0 = *(const float4*)(vxl + src), v1 = *(const float4*)(vxl + src + 4);
                k0.x += p0.x; k0.y += p0.y; k0.z += p0.z; k0.w += p0.w;
                k1.x += p1.x; k1.y += p1.y; k1.z += p1.z; k1.w += p1.w;
                size_t dst = ((size_t)((b * NHEADS + h) * KVLEN + t)) * HD + d8 * 8;
                *(uint4*)&g_kh[dst] = cvt8(k0, k1);
                *(uint4*)&g_vh[dst] = cvt8(v0, v1);
            }
        }
        signal_cnt(32);
    } else if (bid < 816) {
        // ---- qkv GEMM, HEAD-MAJOR column order:
        //      sequence c -> column (c%3)*16 + c/3, so head h's q/k/v
        //      columns are contiguous -> head counters complete early.
        int q = bid - 48;
        int c = q >> 4, row = q & 15;
        int hh = c / 3, rg = c - 3 * hh;
        int col = rg * 16 + hh;
        gemm_body<1>(smraw, ah, bh, nullptr, cosb, sinb,
                     row * 128, col * 128, 3 * D_MODEL);
        signal_cnt(hh);
    } else if (bid < 1072) {
        // ---- attention, h-major order ----
        int a = bid - 816;
        int h = a >> 4, rest = a & 15;
        int b = rest >> 3, qt = rest & 7;
        wait_cnt(h, 48);
        attn_body(smraw, qt, b * 16 + h, *flag);
        signal_cnt(16 + b * 8 + qt);
    } else {
        // ---- proj GEMM ----
        int p = bid - 1072;
        int m = p >> 4, nc = p & 15;
        wait_cnt(16 + m, 16);
        gemm_body<0>(smraw, g_yh, g_bp, out, nullptr, nullptr,
                     m * 128, nc * 128, D_MODEL);
    }
}

// =====================================================================
// launch
// =====================================================================
extern "C" void kernel_launch(void* const* d_in, const int* in_sizes, int n_in,
                              void* d_out, int out_size)
{
    const float* x     = (const float*)d_in[0];
    const float* cosb  = (const float*)d_in[1];
    const float* sinb  = (const float*)d_in[2];
    const float* kxl   = (const float*)d_in[3];
    const float* vxl   = (const float*)d_in[4];
    const float* pos   = (const float*)d_in[5];
    const float* wqkv  = (const float*)d_in[6];
    const float* wproj = (const float*)d_in[7];
    const int*   flag  = (const int*)d_in[8];
    float*       out   = (float*)d_out;

    __half *ah, *bh;
    cudaGetSymbolAddress((void**)&ah, g_ah);
    cudaGetSymbolAddress((void**)&bh, g_bh);

    cudaFuncSetAttribute(mega_kernel, cudaFuncAttributeMaxDynamicSharedMemorySize, MEGA_SMEM);

    // 1) zero counters + convert x + wqkv
    prep1_kernel<<<4096, 256>>>(x, wqkv);

    // 2) everything else: aux + qkv + attn + proj with in-kernel deps
    mega_kernel<<<1328, 256, MEGA_SMEM>>>(ah, bh, cosb, sinb, wproj,
                                          kxl, vxl, pos, flag, out);
}